// round 3
// baseline (speedup 1.0000x reference)
#include <cuda_runtime.h>

#define NN 4096
#define BB 4
#define C_IN 128
#define C_OUT 64
#define ROWCHUNKS 32
#define ITILE 128

typedef unsigned long long ull;

// ---------------- scratch -----------------------------------------------------
__device__ float g_h   [BB * NN * C_OUT];
__device__ float g_f1  [BB * NN];
__device__ float g_f2  [BB * NN];
__device__ float g_Sp  [ROWCHUNKS * BB * NN];
__device__ float g_rS  [BB * NN];

// ---------------- packed f32x2 helpers ----------------------------------------
__device__ __forceinline__ ull pack2(float v) {
    ull r;
    asm("mov.b64 %0, {%1, %1};" : "=l"(r) : "r"(__float_as_uint(v)));
    return r;
}
__device__ __forceinline__ void ffma2(ull& d, ull a, ull b) {
    asm("fma.rn.f32x2 %0, %1, %2, %0;" : "+l"(d) : "l"(a), "l"(b));
}

// E = exp(sigmoid(x)-0.5), x = a*(f1+f2).
// sigmoid(x)-0.5 = 0.5*(1-u)/(1+u), u = e^-x.  E = exp(s/2), s=(1-u)/(1+u) in [-1,1].
// 2 MUFU (EX2, RCP) + Horner deg-5 (5 FMA). |err| < 3e-5.
__device__ __forceinline__ float e_of(float a, float f12) {
    float x = a * f12;
    x = fminf(fmaxf(x, -30.0f), 30.0f);
    float u = __expf(-x);
    float s = __fdividef(1.0f - u, 1.0f + u);
    // exp(s/2): coeffs 1, 1/2, 1/8, 1/48, 1/384, 1/3840
    float p = fmaf(s, 2.604166667e-4f, 2.604166667e-3f);
    p = fmaf(p, s, 2.083333333e-2f);
    p = fmaf(p, s, 0.125f);
    p = fmaf(p, s, 0.5f);
    p = fmaf(p, s, 1.0f);
    return p;
}

// ---------------- kernel 1: h = node_rep @ proj_W^T + proj_b -------------------
__global__ __launch_bounds__(256) void k_proj(const float* __restrict__ node_rep,
                                              const float* __restrict__ proj_W,
                                              const float* __restrict__ proj_b) {
    __shared__ float pw[C_OUT][C_IN + 1];
    __shared__ float nr[16][C_IN];
    int tid = threadIdx.x;
    for (int k = tid; k < C_OUT * C_IN; k += 256)
        pw[k / C_IN][k % C_IN] = proj_W[k];
    int row0 = blockIdx.x * 16;
    for (int k = tid; k < 16 * C_IN; k += 256)
        nr[k / C_IN][k % C_IN] = node_rep[(row0 + k / C_IN) * C_IN + (k % C_IN)];
    __syncthreads();

    int o  = tid & 63;
    int rg = tid >> 6;
    float bias = proj_b[o];
    #pragma unroll
    for (int rr = 0; rr < 4; rr++) {
        int r = rg * 4 + rr;
        float acc = bias;
        #pragma unroll 16
        for (int c = 0; c < C_IN; c++) acc += nr[r][c] * pw[o][c];
        g_h[(row0 + r) * C_OUT + o] = acc;
    }
}

// ---------------- kernel 2: f1/f2 own-type gate scalars ------------------------
__global__ __launch_bounds__(256) void k_scores(const int*   __restrict__ node_type,
                                                const float* __restrict__ k_W,
                                                const float* __restrict__ k_b,
                                                const float* __restrict__ v_W,
                                                const float* __restrict__ v_b) {
    int warp = threadIdx.x >> 5;
    int lane = threadIdx.x & 31;
    int row  = blockIdx.x * 8 + warp;
    int t = node_type[row & (NN - 1)];
    float h0 = g_h[row * 64 + lane];
    float h1 = g_h[row * 64 + lane + 32];
    float p1 = h0 * k_W[t * 64 + lane] + h1 * k_W[t * 64 + lane + 32];
    float p2 = h0 * v_W[t * 64 + lane] + h1 * v_W[t * 64 + lane + 32];
    #pragma unroll
    for (int off = 16; off; off >>= 1) {
        p1 += __shfl_down_sync(0xffffffffu, p1, off);
        p2 += __shfl_down_sync(0xffffffffu, p2, off);
    }
    if (lane == 0) {
        g_f1[row] = p1 + k_b[t];
        g_f2[row] = p2 + v_b[t];
    }
}

// ---------------- kernel 3: partial column sums --------------------------------
__global__ __launch_bounds__(128) void k_colsum(const float* __restrict__ adj) {
    int j  = blockIdx.x * 128 + threadIdx.x;
    int rc = blockIdx.y;
    float f2v[BB], s[BB];
    #pragma unroll
    for (int b = 0; b < BB; b++) { f2v[b] = g_f2[b * NN + j]; s[b] = 0.0f; }
    int i0 = rc * 128;
    for (int ii = 0; ii < 128; ii++) {
        int i = i0 + ii;
        float a = adj[i * NN + j];
        #pragma unroll
        for (int b = 0; b < BB; b++)
            s[b] += e_of(a, g_f1[b * NN + i] + f2v[b]);
    }
    #pragma unroll
    for (int b = 0; b < BB; b++)
        g_Sp[(rc * BB + b) * NN + j] = s[b];
}

// ---------------- kernel 4: rS = 1/S --------------------------------------------
__global__ __launch_bounds__(256) void k_reduceS() {
    int idx = blockIdx.x * 256 + threadIdx.x;
    float s = 0.0f;
    #pragma unroll
    for (int rc = 0; rc < ROWCHUNKS; rc++) s += g_Sp[rc * BB * NN + idx];
    g_rS[idx] = __fdividef(1.0f, s);
}

// ---------------- kernel 5: out = E @ (h * rS), packed f32x2 --------------------
// Tile: 128 i-rows x 64 o, j-chunks of 64. 256 threads.
// Thread: ox = tid&3 -> o in [ox*16, ox*16+16);  iy = tid>>2 -> i = iy*2 + {0,1}.
#define ESTRIDE 66
__global__ __launch_bounds__(256) void k_main(const float* __restrict__ adj,
                                              float* __restrict__ out) {
    __shared__ float Es[ITILE][ESTRIDE];   // E tile, padded stride
    __shared__ float Hs[64][64];           // h*rS tile [j][o]
    __shared__ float f1s[ITILE];

    int tid = threadIdx.x;
    int it  = blockIdx.x;        // 0..31
    int b   = blockIdx.y;        // 0..3
    int i0  = it * ITILE;

    int ox = tid & 3;
    int iy = tid >> 2;

    // preload f1 (+nothing else changes across chunks)
    if (tid < ITILE) f1s[tid] = g_f1[b * NN + i0 + tid];
    __syncthreads();

    ull acc[2][8];
    #pragma unroll
    for (int r = 0; r < 2; r++)
        #pragma unroll
        for (int q = 0; q < 8; q++) acc[r][q] = 0ull;

    const float4* adj4 = (const float4*)adj;
    const float4* f24  = (const float4*)(g_f2 + b * NN);
    const float4* h4   = (const float4*)(g_h + (size_t)b * NN * 64);
    const float*  rS   = g_rS + b * NN;

    for (int jc = 0; jc < 64; jc++) {
        int j0 = jc * 64;
        __syncthreads();

        // ---- build E tile: 128x64 = 2048 float4, 8 per thread ----
        #pragma unroll
        for (int k = 0; k < 8; k++) {
            int idx4 = tid + 256 * k;          // 0..2047
            int i  = idx4 >> 4;                // 0..127
            int jq = idx4 & 15;
            float4 a  = adj4[((size_t)(i0 + i) * NN + j0) / 4 + jq];
            float4 f2 = f24[j0 / 4 + jq];
            float  f1 = f1s[i];
            float2 e01, e23;
            e01.x = e_of(a.x, f1 + f2.x);
            e01.y = e_of(a.y, f1 + f2.y);
            e23.x = e_of(a.z, f1 + f2.z);
            e23.y = e_of(a.w, f1 + f2.w);
            float2* p = (float2*)&Es[i][jq * 4];
            p[0] = e01;
            p[1] = e23;
        }
        // ---- build H tile: 64x64 = 1024 float4, 4 per thread, scaled by rS ----
        #pragma unroll
        for (int k = 0; k < 4; k++) {
            int idx4 = tid + 256 * k;          // 0..1023
            int jj = idx4 >> 4;
            int q  = idx4 & 15;
            float4 h = h4[(size_t)(j0 + jj) * 16 + q];
            float  r = rS[j0 + jj];
            h.x *= r; h.y *= r; h.z *= r; h.w *= r;
            ((float4*)Hs)[jj * 16 + q] = h;
        }
        __syncthreads();

        // ---- compute: 64 j-steps, 16 FFMA2 + 2 packs each ----
        const float* e0row = &Es[iy * 2][0];
        const float* e1row = &Es[iy * 2 + 1][0];
        #pragma unroll 8
        for (int j = 0; j < 64; j++) {
            ull p0 = pack2(e0row[j]);
            ull p1 = pack2(e1row[j]);
            const ull* hrow = (const ull*)&Hs[j][ox * 16];
            #pragma unroll
            for (int q = 0; q < 8; q++) {
                ull hv = hrow[q];
                ffma2(acc[0][q], p0, hv);
                ffma2(acc[1][q], p1, hv);
            }
        }
    }

    // ---- store: 2 i-rows x 16 o (8 float2 each) ----
    #pragma unroll
    for (int r = 0; r < 2; r++) {
        size_t row = (size_t)b * NN + i0 + iy * 2 + r;
        float2* o2 = (float2*)(out + row * 64 + ox * 16);
        #pragma unroll
        for (int q = 0; q < 8; q++) {
            float2 v;
            v.x = __uint_as_float((unsigned)(acc[r][q] & 0xffffffffull));
            v.y = __uint_as_float((unsigned)(acc[r][q] >> 32));
            o2[q] = v;
        }
    }
}

// ---------------- launch ---------------------------------------------------------
extern "C" void kernel_launch(void* const* d_in, const int* in_sizes, int n_in,
                              void* d_out, int out_size) {
    const float* node_rep = (const float*)d_in[0];
    const float* adj      = (const float*)d_in[1];
    const int*   node_ty  = (const int*)  d_in[2];
    const float* proj_W   = (const float*)d_in[3];
    const float* proj_b   = (const float*)d_in[4];
    const float* k_W      = (const float*)d_in[5];
    const float* k_b      = (const float*)d_in[6];
    const float* v_W      = (const float*)d_in[7];
    const float* v_b      = (const float*)d_in[8];
    float* out = (float*)d_out;

    k_proj   <<<(BB * NN) / 16, 256>>>(node_rep, proj_W, proj_b);
    k_scores <<<(BB * NN) / 8, 256>>>(node_ty, k_W, k_b, v_W, v_b);
    k_colsum <<<dim3(NN / 128, ROWCHUNKS), 128>>>(adj);
    k_reduceS<<<(BB * NN) / 256, 256>>>();
    k_main   <<<dim3(NN / ITILE, BB), 256>>>(adj, out);
}

// round 6
// speedup vs baseline: 3.0666x; 3.0666x over previous
#include <cuda_runtime.h>
#include <cuda_fp16.h>
#include <cstdint>

#define NN 4096
#define BB 4
#define C_IN 128
#define C_OUT 64
#define ROWCHUNKS 32
#define ITILE 128
#define ESTR 72   // padded half-stride: 144B rows -> conflict-free ldmatrix

// ---------------- scratch -----------------------------------------------------
__device__ float g_h   [BB * NN * C_OUT];
__device__ float g_f1  [BB * NN];
__device__ float g_f2  [BB * NN];
__device__ float g_Sp  [ROWCHUNKS * BB * NN];
__device__ float g_rS  [BB * NN];   // 4096 / S  (power-of-2 pre-scale for fp16)

// ---------------- helpers ------------------------------------------------------
__device__ __forceinline__ uint32_t smem_u32(const void* p) {
    uint32_t a;
    asm("{ .reg .u64 t; cvta.to.shared.u64 t, %1; cvt.u32.u64 %0, t; }" : "=r"(a) : "l"(p));
    return a;
}
__device__ __forceinline__ uint32_t pack_f16(float lo, float hi) {
    uint32_t r;
    asm("cvt.rn.f16x2.f32 %0, %1, %2;" : "=r"(r) : "f"(hi), "f"(lo));
    return r;
}
__device__ __forceinline__ void ldsm4(uint32_t* r, uint32_t addr) {
    asm volatile("ldmatrix.sync.aligned.m8n8.x4.shared.b16 {%0,%1,%2,%3}, [%4];"
        : "=r"(r[0]), "=r"(r[1]), "=r"(r[2]), "=r"(r[3]) : "r"(addr));
}
__device__ __forceinline__ void mma16816(float* c, const uint32_t* a, uint32_t b0, uint32_t b1) {
    asm volatile("mma.sync.aligned.m16n8k16.row.col.f32.f16.f16.f32 "
        "{%0,%1,%2,%3}, {%4,%5,%6,%7}, {%8,%9}, {%0,%1,%2,%3};"
        : "+f"(c[0]), "+f"(c[1]), "+f"(c[2]), "+f"(c[3])
        : "r"(a[0]), "r"(a[1]), "r"(a[2]), "r"(a[3]), "r"(b0), "r"(b1));
}

// E = exp(sigmoid(x)-0.5): 2 MUFU + deg-5 Horner. |elem err| < 3e-5 (R3-validated).
__device__ __forceinline__ float e_of(float a, float f12) {
    float x = a * f12;
    x = fminf(fmaxf(x, -30.0f), 30.0f);
    float u = __expf(-x);
    float s = __fdividef(1.0f - u, 1.0f + u);
    float p = fmaf(s, 2.604166667e-4f, 2.604166667e-3f);
    p = fmaf(p, s, 2.083333333e-2f);
    p = fmaf(p, s, 0.125f);
    p = fmaf(p, s, 0.5f);
    p = fmaf(p, s, 1.0f);
    return p;
}

// ---------------- kernel 1: h = node_rep @ proj_W^T + proj_b -------------------
__global__ __launch_bounds__(256) void k_proj(const float* __restrict__ node_rep,
                                              const float* __restrict__ proj_W,
                                              const float* __restrict__ proj_b) {
    __shared__ float pw[C_OUT][C_IN + 1];
    __shared__ float nr[16][C_IN];
    int tid = threadIdx.x;
    for (int k = tid; k < C_OUT * C_IN; k += 256)
        pw[k / C_IN][k % C_IN] = proj_W[k];
    int row0 = blockIdx.x * 16;
    for (int k = tid; k < 16 * C_IN; k += 256)
        nr[k / C_IN][k % C_IN] = node_rep[(row0 + k / C_IN) * C_IN + (k % C_IN)];
    __syncthreads();
    int o  = tid & 63;
    int rg = tid >> 6;
    float bias = proj_b[o];
    #pragma unroll
    for (int rr = 0; rr < 4; rr++) {
        int r = rg * 4 + rr;
        float acc = bias;
        #pragma unroll 16
        for (int c = 0; c < C_IN; c++) acc += nr[r][c] * pw[o][c];
        g_h[(row0 + r) * C_OUT + o] = acc;
    }
}

// ---------------- kernel 2: f1/f2 own-type gate scalars ------------------------
__global__ __launch_bounds__(256) void k_scores(const int*   __restrict__ node_type,
                                                const float* __restrict__ k_W,
                                                const float* __restrict__ k_b,
                                                const float* __restrict__ v_W,
                                                const float* __restrict__ v_b) {
    int warp = threadIdx.x >> 5;
    int lane = threadIdx.x & 31;
    int row  = blockIdx.x * 8 + warp;
    int t = node_type[row & (NN - 1)];
    float h0 = g_h[row * 64 + lane];
    float h1 = g_h[row * 64 + lane + 32];
    float p1 = h0 * k_W[t * 64 + lane] + h1 * k_W[t * 64 + lane + 32];
    float p2 = h0 * v_W[t * 64 + lane] + h1 * v_W[t * 64 + lane + 32];
    #pragma unroll
    for (int off = 16; off; off >>= 1) {
        p1 += __shfl_down_sync(0xffffffffu, p1, off);
        p2 += __shfl_down_sync(0xffffffffu, p2, off);
    }
    if (lane == 0) {
        g_f1[row] = p1 + k_b[t];
        g_f2[row] = p2 + v_b[t];
    }
}

// ---------------- kernel 3: partial column sums --------------------------------
__global__ __launch_bounds__(128) void k_colsum(const float* __restrict__ adj) {
    int j  = blockIdx.x * 128 + threadIdx.x;
    int rc = blockIdx.y;
    float f2v[BB], s[BB];
    #pragma unroll
    for (int b = 0; b < BB; b++) { f2v[b] = g_f2[b * NN + j]; s[b] = 0.0f; }
    int i0 = rc * 128;
    for (int ii = 0; ii < 128; ii++) {
        int i = i0 + ii;
        float a = adj[i * NN + j];
        #pragma unroll
        for (int b = 0; b < BB; b++)
            s[b] += e_of(a, g_f1[b * NN + i] + f2v[b]);
    }
    #pragma unroll
    for (int b = 0; b < BB; b++)
        g_Sp[(rc * BB + b) * NN + j] = s[b];
}

// ---------------- kernel 4: rS = 4096/S (pow2 pre-scale) ------------------------
__global__ __launch_bounds__(256) void k_reduceS() {
    int idx = blockIdx.x * 256 + threadIdx.x;
    float s = 0.0f;
    #pragma unroll
    for (int rc = 0; rc < ROWCHUNKS; rc++) s += g_Sp[rc * BB * NN + idx];
    g_rS[idx] = __fdividef(4096.0f, s);
}

// ---------------- kernel 5: out = E @ h2^T via mma.sync fp16 --------------------
// CTA: 128 i x 64 o. 8 warps: mw = wid&3 (i 32-block), nw = wid>>2 (o 32-block).
__global__ __launch_bounds__(256, 1)
void k_main_mma(const float* __restrict__ adj, float* __restrict__ out) {
    __shared__ __align__(16) uint16_t Es[ITILE * ESTR];  // E tile [i][j], fp16 bits
    __shared__ __align__(16) uint16_t Hs[64 * ESTR];     // h2^T tile [o][j], fp16 bits
    __shared__ float f1s[ITILE];

    int tid  = threadIdx.x;
    int wid  = tid >> 5;
    int lane = tid & 31;
    int it = blockIdx.x, b = blockIdx.y;
    int i0 = it * ITILE;

    int mw = wid & 3;
    int nw = wid >> 2;

    if (tid < ITILE) f1s[tid] = g_f1[b * NN + i0 + tid];

    const float4* adj4 = (const float4*)adj;
    const float4* f24  = (const float4*)(g_f2 + b * NN);
    const float4* h4   = (const float4*)(g_h + (size_t)b * NN * 64);
    const float*  rS   = g_rS + b * NN;

    uint32_t eA = smem_u32(Es);
    uint32_t hB = smem_u32(Hs);

    // staging decomposition
    int si = tid >> 4;            // E: i row per 16-thread group (x8 -> 128 rows)
    int sjq = tid & 15;           // E: float4 column
    int oq = tid >> 5, jp = tid & 31;  // H: o-octet, j-pair

    float acc[2][4][4];
    #pragma unroll
    for (int mt = 0; mt < 2; mt++)
        #pragma unroll
        for (int nt = 0; nt < 4; nt++)
            #pragma unroll
            for (int q = 0; q < 4; q++) acc[mt][nt][q] = 0.0f;

    // prologue: prefetch adj for chunk 0
    float4 pa[8];
    #pragma unroll
    for (int k2 = 0; k2 < 8; k2++)
        pa[k2] = adj4[(size_t)(i0 + si + 16 * k2) * (NN / 4) + sjq];

    for (int c = 0; c < 64; c++) {
        int j0 = c * 64;
        __syncthreads();   // previous MMA phase done reading smem

        // ---- stage H tile: [64 o][64 j], transposed + rS-scaled ----
        {
            int r0 = j0 + 2 * jp, r1 = r0 + 1;
            float s0 = rS[r0], s1 = rS[r1];
            float4 a0 = h4[(size_t)r0 * 16 + oq * 2];
            float4 a1 = h4[(size_t)r0 * 16 + oq * 2 + 1];
            float4 c0 = h4[(size_t)r1 * 16 + oq * 2];
            float4 c1 = h4[(size_t)r1 * 16 + oq * 2 + 1];
            float va[8] = {a0.x*s0, a0.y*s0, a0.z*s0, a0.w*s0, a1.x*s0, a1.y*s0, a1.z*s0, a1.w*s0};
            float vb[8] = {c0.x*s1, c0.y*s1, c0.z*s1, c0.w*s1, c1.x*s1, c1.y*s1, c1.z*s1, c1.w*s1};
            #pragma unroll
            for (int k = 0; k < 8; k++) {
                int o = oq * 8 + k;
                *(uint32_t*)&Hs[o * ESTR + 2 * jp] = pack_f16(va[k], vb[k]);
            }
        }
        // ---- stage E tile: [128 i][64 j] fp16 from prefetched adj ----
        #pragma unroll
        for (int k2 = 0; k2 < 8; k2++) {
            int i = si + 16 * k2;
            float4 a  = pa[k2];
            float4 f2 = f24[j0 / 4 + sjq];
            float  f1 = f1s[i];
            float e0 = e_of(a.x, f1 + f2.x);
            float e1 = e_of(a.y, f1 + f2.y);
            float e2 = e_of(a.z, f1 + f2.z);
            float e3 = e_of(a.w, f1 + f2.w);
            *(uint2*)&Es[i * ESTR + sjq * 4] =
                make_uint2(pack_f16(e0, e1), pack_f16(e2, e3));
        }
        __syncthreads();   // tiles ready

        // ---- prefetch adj for next chunk (overlaps MMA phase) ----
        if (c + 1 < 64) {
            #pragma unroll
            for (int k2 = 0; k2 < 8; k2++)
                pa[k2] = adj4[(size_t)(i0 + si + 16 * k2) * (NN / 4) + (c + 1) * 16 + sjq];
        }

        // ---- MMA phase: K=64 in 4 k16 steps ----
        int rowl = lane & 15;
        int koff = 8 * (lane >> 4);
        #pragma unroll
        for (int ks = 0; ks < 4; ks++) {
            int kb = ks * 16 + koff;
            uint32_t af[2][4], bf[2][4];
            ldsm4(af[0], eA + (uint32_t)(((mw * 32 +  0 + rowl) * ESTR + kb) * 2));
            ldsm4(af[1], eA + (uint32_t)(((mw * 32 + 16 + rowl) * ESTR + kb) * 2));
            ldsm4(bf[0], hB + (uint32_t)(((nw * 32 +  0 + rowl) * ESTR + kb) * 2));
            ldsm4(bf[1], hB + (uint32_t)(((nw * 32 + 16 + rowl) * ESTR + kb) * 2));
            #pragma unroll
            for (int mt = 0; mt < 2; mt++) {
                mma16816(acc[mt][0], af[mt], bf[0][0], bf[0][2]);
                mma16816(acc[mt][1], af[mt], bf[0][1], bf[0][3]);
                mma16816(acc[mt][2], af[mt], bf[1][0], bf[1][2]);
                mma16816(acc[mt][3], af[mt], bf[1][1], bf[1][3]);
            }
        }
    }

    // ---- epilogue: undo 4096 pre-scale (exact pow2), store f32 ----
    const float sc = 1.0f / 4096.0f;
    int rr = lane >> 2;
    int cc = (lane & 3) * 2;
    #pragma unroll
    for (int mt = 0; mt < 2; mt++) {
        #pragma unroll
        for (int nt = 0; nt < 4; nt++) {
            size_t row = (size_t)b * NN + i0 + mw * 32 + mt * 16 + rr;
            int col = nw * 32 + nt * 8 + cc;
            *(float2*)(out + row * 64 + col) =
                make_float2(acc[mt][nt][0] * sc, acc[mt][nt][1] * sc);
            *(float2*)(out + (row + 8) * 64 + col) =
                make_float2(acc[mt][nt][2] * sc, acc[mt][nt][3] * sc);
        }
    }
}

// ---------------- launch ---------------------------------------------------------
extern "C" void kernel_launch(void* const* d_in, const int* in_sizes, int n_in,
                              void* d_out, int out_size) {
    const float* node_rep = (const float*)d_in[0];
    const float* adj      = (const float*)d_in[1];
    const int*   node_ty  = (const int*)  d_in[2];
    const float* proj_W   = (const float*)d_in[3];
    const float* proj_b   = (const float*)d_in[4];
    const float* k_W      = (const float*)d_in[5];
    const float* k_b      = (const float*)d_in[6];
    const float* v_W      = (const float*)d_in[7];
    const float* v_b      = (const float*)d_in[8];
    float* out = (float*)d_out;

    k_proj    <<<(BB * NN) / 16, 256>>>(node_rep, proj_W, proj_b);
    k_scores  <<<(BB * NN) / 8, 256>>>(node_ty, k_W, k_b, v_W, v_b);
    k_colsum  <<<dim3(NN / 128, ROWCHUNKS), 128>>>(adj);
    k_reduceS <<<(BB * NN) / 256, 256>>>();
    k_main_mma<<<dim3(NN / ITILE, BB), 256>>>(adj, out);
}

// round 7
// speedup vs baseline: 3.7530x; 1.2238x over previous
#include <cuda_runtime.h>
#include <cuda_fp16.h>
#include <cstdint>

#define NN 4096
#define BB 4
#define C_IN 128
#define C_OUT 64
#define ROWCHUNKS 32
#define ITILE 128
#define ESTR 72           // padded half-stride (144B rows): conflict-free ldmatrix
#define EBYTES (ITILE * ESTR * 2)          // 18432
#define HBYTES (64 * ESTR * 2)             // 9216
#define BUFB   (EBYTES + HBYTES)           // 27648
#define SMEM_DYN (2 * BUFB)                // 55296

// ---------------- scratch -----------------------------------------------------
__device__ float    g_h  [BB * NN * C_OUT];
__device__ float    g_f1 [BB * NN];          // 0.5 * own-type k score
__device__ float    g_f2 [BB * NN];          // 0.5 * own-type v score
__device__ float    g_Sp [ROWCHUNKS * BB * NN];
__device__ float    g_rS [BB * NN];          // 4096 / S
__device__ uint16_t g_hT [BB * 64 * NN];     // fp16 (h*rS)^T, [b][o][j]

// ---------------- helpers ------------------------------------------------------
__device__ __forceinline__ uint32_t smem_u32(const void* p) {
    uint32_t a;
    asm("{ .reg .u64 t; cvta.to.shared.u64 t, %1; cvt.u32.u64 %0, t; }" : "=r"(a) : "l"(p));
    return a;
}
__device__ __forceinline__ uint32_t pack_f16(float lo, float hi) {
    uint32_t r;
    asm("cvt.rn.f16x2.f32 %0, %1, %2;" : "=r"(r) : "f"(hi), "f"(lo));
    return r;
}
__device__ __forceinline__ void ldsm4(uint32_t* r, uint32_t addr) {
    asm volatile("ldmatrix.sync.aligned.m8n8.x4.shared.b16 {%0,%1,%2,%3}, [%4];"
        : "=r"(r[0]), "=r"(r[1]), "=r"(r[2]), "=r"(r[3]) : "r"(addr));
}
__device__ __forceinline__ void mma16816(float* c, const uint32_t* a, uint32_t b0, uint32_t b1) {
    asm volatile("mma.sync.aligned.m16n8k16.row.col.f32.f16.f16.f32 "
        "{%0,%1,%2,%3}, {%4,%5,%6,%7}, {%8,%9}, {%0,%1,%2,%3};"
        : "+f"(c[0]), "+f"(c[1]), "+f"(c[2]), "+f"(c[3])
        : "r"(a[0]), "r"(a[1]), "r"(a[2]), "r"(a[3]), "r"(b0), "r"(b1));
}

// E = exp(sigmoid(x)-0.5) with x = a*(f1+f2) and f-values pre-halved:
//   xh = a*f12h = x/2;  tanh(xh) = 2*sigmoid(x)-1  =>  E = exp2(tanh(xh)*log2(e)/2)
// 3 FMA-pipe + 2 MUFU (TANH, EX2).
__device__ __forceinline__ float e_of(float a, float f12h) {
    float xh = a * f12h, t, r;
    asm("tanh.approx.f32 %0, %1;" : "=f"(t) : "f"(xh));
    float y = t * 0.72134752f;
    asm("ex2.approx.f32 %0, %1;" : "=f"(r) : "f"(y));
    return r;
}

// ---------------- kernel 1: h = node_rep @ proj_W^T + proj_b -------------------
__global__ __launch_bounds__(256) void k_proj(const float* __restrict__ node_rep,
                                              const float* __restrict__ proj_W,
                                              const float* __restrict__ proj_b) {
    __shared__ float pw[C_OUT][C_IN + 1];
    __shared__ float nr[16][C_IN];
    int tid = threadIdx.x;
    for (int k = tid; k < C_OUT * C_IN; k += 256)
        pw[k / C_IN][k % C_IN] = proj_W[k];
    int row0 = blockIdx.x * 16;
    for (int k = tid; k < 16 * C_IN; k += 256)
        nr[k / C_IN][k % C_IN] = node_rep[(row0 + k / C_IN) * C_IN + (k % C_IN)];
    __syncthreads();
    int o  = tid & 63;
    int rg = tid >> 6;
    float bias = proj_b[o];
    #pragma unroll
    for (int rr = 0; rr < 4; rr++) {
        int r = rg * 4 + rr;
        float acc = bias;
        #pragma unroll 16
        for (int c = 0; c < C_IN; c++) acc += nr[r][c] * pw[o][c];
        g_h[(row0 + r) * C_OUT + o] = acc;
    }
}

// ---------------- kernel 2: halved own-type gate scalars -----------------------
__global__ __launch_bounds__(256) void k_scores(const int*   __restrict__ node_type,
                                                const float* __restrict__ k_W,
                                                const float* __restrict__ k_b,
                                                const float* __restrict__ v_W,
                                                const float* __restrict__ v_b) {
    int warp = threadIdx.x >> 5;
    int lane = threadIdx.x & 31;
    int row  = blockIdx.x * 8 + warp;
    int t = node_type[row & (NN - 1)];
    float h0 = g_h[row * 64 + lane];
    float h1 = g_h[row * 64 + lane + 32];
    float p1 = h0 * k_W[t * 64 + lane] + h1 * k_W[t * 64 + lane + 32];
    float p2 = h0 * v_W[t * 64 + lane] + h1 * v_W[t * 64 + lane + 32];
    #pragma unroll
    for (int off = 16; off; off >>= 1) {
        p1 += __shfl_down_sync(0xffffffffu, p1, off);
        p2 += __shfl_down_sync(0xffffffffu, p2, off);
    }
    if (lane == 0) {
        g_f1[row] = 0.5f * (p1 + k_b[t]);
        g_f2[row] = 0.5f * (p2 + v_b[t]);
    }
}

// ---------------- kernel 3: partial column sums --------------------------------
__global__ __launch_bounds__(128) void k_colsum(const float* __restrict__ adj) {
    int j  = blockIdx.x * 128 + threadIdx.x;
    int rc = blockIdx.y;
    float f2v[BB], s[BB];
    #pragma unroll
    for (int b = 0; b < BB; b++) { f2v[b] = g_f2[b * NN + j]; s[b] = 0.0f; }
    int i0 = rc * 128;
    for (int ii = 0; ii < 128; ii++) {
        int i = i0 + ii;
        float a = adj[i * NN + j];
        #pragma unroll
        for (int b = 0; b < BB; b++)
            s[b] += e_of(a, g_f1[b * NN + i] + f2v[b]);
    }
    #pragma unroll
    for (int b = 0; b < BB; b++)
        g_Sp[(rc * BB + b) * NN + j] = s[b];
}

// ---------------- kernel 4: rS = 4096/S ------------------------------------------
__global__ __launch_bounds__(256) void k_reduceS() {
    int idx = blockIdx.x * 256 + threadIdx.x;
    float s = 0.0f;
    #pragma unroll
    for (int rc = 0; rc < ROWCHUNKS; rc++) s += g_Sp[rc * BB * NN + idx];
    g_rS[idx] = __fdividef(4096.0f, s);
}

// ---------------- kernel 4b: g_hT[b][o][j] = fp16(h[b][j][o] * rS[b][j]) --------
__global__ __launch_bounds__(256) void k_prep() {
    int idx = blockIdx.x * 256 + threadIdx.x;      // over BB*64*NN/2
    int jp = idx & (NN / 2 - 1);
    int bo = idx / (NN / 2);
    int o = bo & 63, b = bo >> 6;
    int j0 = jp * 2;
    float r0 = g_rS[b * NN + j0], r1 = g_rS[b * NN + j0 + 1];
    float v0 = g_h[((size_t)b * NN + j0) * 64 + o] * r0;
    float v1 = g_h[((size_t)b * NN + j0 + 1) * 64 + o] * r1;
    *(uint32_t*)&g_hT[((size_t)b * 64 + o) * NN + j0] = pack_f16(v0, v1);
}

// ---------------- kernel 5: out = E @ h2^T, pipelined HMMA ----------------------
__global__ __launch_bounds__(256, 1)
void k_main_mma(const float* __restrict__ adj, float* __restrict__ out) {
    extern __shared__ __align__(16) char dyn[];
    __shared__ float f1s[ITILE];

    int tid  = threadIdx.x;
    int wid  = tid >> 5;
    int lane = tid & 31;
    int it = blockIdx.x, b = blockIdx.y;
    int i0 = it * ITILE;

    int mw = wid & 3;
    int nw = wid >> 2;

    if (tid < ITILE) f1s[tid] = g_f1[b * NN + i0 + tid];

    const float4* adj4 = (const float4*)adj;
    const float4* f24  = (const float4*)(g_f2 + b * NN);

    uint32_t base = smem_u32(dyn);
    uint32_t eA[2] = { base,         base + BUFB };
    uint32_t hB[2] = { base + EBYTES, base + BUFB + EBYTES };
    uint16_t* Ep[2] = { (uint16_t*)dyn,            (uint16_t*)(dyn + BUFB) };
    uint16_t* Hp[2] = { (uint16_t*)(dyn + EBYTES), (uint16_t*)(dyn + BUFB + EBYTES) };

    // staging decomposition
    int si  = tid >> 4;               // E: base i-row (x8 strided by 16)
    int sjq = tid & 15;               // E: float4 column
    int ho  = tid >> 2;               // H: o row (0..63)
    int hseg = tid & 3;               // H: 16-half segment
    const uint4* hsrc = (const uint4*)&g_hT[((size_t)b * 64 + ho) * NN];

    float acc[2][4][4];
    #pragma unroll
    for (int mt = 0; mt < 2; mt++)
        #pragma unroll
        for (int nt = 0; nt < 4; nt++)
            #pragma unroll
            for (int q = 0; q < 4; q++) acc[mt][nt][q] = 0.0f;

    float4 pa[8];
    #pragma unroll
    for (int k2 = 0; k2 < 8; k2++)
        pa[k2] = adj4[(size_t)(i0 + si + 16 * k2) * (NN / 4) + sjq];
    __syncthreads();   // f1s ready

    // ---- stage chunk 0 into buf 0 ----
    {
        float4 f2 = f24[sjq];
        #pragma unroll
        for (int k2 = 0; k2 < 8; k2++) {
            int i = si + 16 * k2;
            float4 a = pa[k2];
            float f1 = f1s[i];
            *(uint2*)&Ep[0][i * ESTR + sjq * 4] = make_uint2(
                pack_f16(e_of(a.x, f1 + f2.x), e_of(a.y, f1 + f2.y)),
                pack_f16(e_of(a.z, f1 + f2.z), e_of(a.w, f1 + f2.w)));
        }
        uint4* hdst = (uint4*)&Hp[0][ho * ESTR + hseg * 16];
        hdst[0] = hsrc[hseg * 2];
        hdst[1] = hsrc[hseg * 2 + 1];
    }
    __syncthreads();

    int rowl = lane & 15;
    int koff = 8 * (lane >> 4);

    for (int c = 0; c < 64; c++) {
        int buf = c & 1;

        // prefetch adj for chunk c+1 (covered by MMA below)
        if (c + 1 < 64) {
            #pragma unroll
            for (int k2 = 0; k2 < 8; k2++)
                pa[k2] = adj4[(size_t)(i0 + si + 16 * k2) * (NN / 4) + (c + 1) * 16 + sjq];
        }

        // ---- MMA on buf(c) ----
        #pragma unroll
        for (int ks = 0; ks < 4; ks++) {
            int kb = ks * 16 + koff;
            uint32_t af[2][4], bf[2][4];
            ldsm4(af[0], eA[buf] + (uint32_t)(((mw * 32 +  0 + rowl) * ESTR + kb) * 2));
            ldsm4(af[1], eA[buf] + (uint32_t)(((mw * 32 + 16 + rowl) * ESTR + kb) * 2));
            ldsm4(bf[0], hB[buf] + (uint32_t)(((nw * 32 +  0 + rowl) * ESTR + kb) * 2));
            ldsm4(bf[1], hB[buf] + (uint32_t)(((nw * 32 + 16 + rowl) * ESTR + kb) * 2));
            #pragma unroll
            for (int mt = 0; mt < 2; mt++) {
                mma16816(acc[mt][0], af[mt], bf[0][0], bf[0][2]);
                mma16816(acc[mt][1], af[mt], bf[0][1], bf[0][3]);
                mma16816(acc[mt][2], af[mt], bf[1][0], bf[1][2]);
                mma16816(acc[mt][3], af[mt], bf[1][1], bf[1][3]);
            }
        }

        // ---- stage chunk c+1 into buf^1 ----
        if (c + 1 < 64) {
            int nb = buf ^ 1;
            int j0q = (c + 1) * 16;
            float4 f2 = f24[j0q + sjq];
            #pragma unroll
            for (int k2 = 0; k2 < 8; k2++) {
                int i = si + 16 * k2;
                float4 a = pa[k2];
                float f1 = f1s[i];
                *(uint2*)&Ep[nb][i * ESTR + sjq * 4] = make_uint2(
                    pack_f16(e_of(a.x, f1 + f2.x), e_of(a.y, f1 + f2.y)),
                    pack_f16(e_of(a.z, f1 + f2.z), e_of(a.w, f1 + f2.w)));
            }
            uint4* hdst = (uint4*)&Hp[nb][ho * ESTR + hseg * 16];
            hdst[0] = hsrc[(c + 1) * 8 + hseg * 2];
            hdst[1] = hsrc[(c + 1) * 8 + hseg * 2 + 1];
        }
        __syncthreads();
    }

    // ---- epilogue: undo 4096 pre-scale (exact pow2), store f32 ----
    const float sc = 1.0f / 4096.0f;
    int rr = lane >> 2;
    int cc = (lane & 3) * 2;
    #pragma unroll
    for (int mt = 0; mt < 2; mt++) {
        #pragma unroll
        for (int nt = 0; nt < 4; nt++) {
            size_t row = (size_t)b * NN + i0 + mw * 32 + mt * 16 + rr;
            int col = nw * 32 + nt * 8 + cc;
            *(float2*)(out + row * 64 + col) =
                make_float2(acc[mt][nt][0] * sc, acc[mt][nt][1] * sc);
            *(float2*)(out + (row + 8) * 64 + col) =
                make_float2(acc[mt][nt][2] * sc, acc[mt][nt][3] * sc);
        }
    }
}

// ---------------- launch ---------------------------------------------------------
extern "C" void kernel_launch(void* const* d_in, const int* in_sizes, int n_in,
                              void* d_out, int out_size) {
    const float* node_rep = (const float*)d_in[0];
    const float* adj      = (const float*)d_in[1];
    const int*   node_ty  = (const int*)  d_in[2];
    const float* proj_W   = (const float*)d_in[3];
    const float* proj_b   = (const float*)d_in[4];
    const float* k_W      = (const float*)d_in[5];
    const float* k_b      = (const float*)d_in[6];
    const float* v_W      = (const float*)d_in[7];
    const float* v_b      = (const float*)d_in[8];
    float* out = (float*)d_out;

    static bool attr_done = false;
    if (!attr_done) {
        cudaFuncSetAttribute(k_main_mma, cudaFuncAttributeMaxDynamicSharedMemorySize, SMEM_DYN);
        attr_done = true;
    }

    k_proj    <<<(BB * NN) / 16, 256>>>(node_rep, proj_W, proj_b);
    k_scores  <<<(BB * NN) / 8, 256>>>(node_ty, k_W, k_b, v_W, v_b);
    k_colsum  <<<dim3(NN / 128, ROWCHUNKS), 128>>>(adj);
    k_reduceS <<<(BB * NN) / 256, 256>>>();
    k_prep    <<<(BB * 64 * NN / 2) / 256, 256>>>();
    k_main_mma<<<dim3(NN / ITILE, BB), 256, SMEM_DYN>>>(adj, out);
}

// round 8
// speedup vs baseline: 4.2917x; 1.1435x over previous
#include <cuda_runtime.h>
#include <cuda_fp16.h>
#include <cstdint>

#define NN 4096
#define BB 4
#define C_IN 128
#define C_OUT 64
#define ROWCHUNKS 32
#define ITILE 64
#define ESTR 72           // padded half-stride (144B rows): conflict-free ldmatrix
#define EBYTES (ITILE * ESTR * 2)          // 9216
#define HBYTES (64 * ESTR * 2)             // 9216
#define BUFB   (EBYTES + HBYTES)           // 18432
#define SMEM_DYN (2 * BUFB)                // 36864

// ---------------- scratch -----------------------------------------------------
__device__ float    g_h  [BB * NN * C_OUT];
__device__ float    g_f1 [BB * NN];          // 0.5 * own-type k score
__device__ float    g_f2 [BB * NN];          // 0.5 * own-type v score
__device__ float    g_Sp [ROWCHUNKS * BB * NN];
__device__ float    g_rS [BB * NN];          // 4096 / S
__device__ uint16_t g_hT [BB * 64 * NN];     // fp16 (h*rS)^T, [b][o][j]

// ---------------- helpers ------------------------------------------------------
__device__ __forceinline__ uint32_t smem_u32(const void* p) {
    uint32_t a;
    asm("{ .reg .u64 t; cvta.to.shared.u64 t, %1; cvt.u32.u64 %0, t; }" : "=r"(a) : "l"(p));
    return a;
}
__device__ __forceinline__ uint32_t pack_f16(float lo, float hi) {
    uint32_t r;
    asm("cvt.rn.f16x2.f32 %0, %1, %2;" : "=r"(r) : "f"(hi), "f"(lo));
    return r;
}
__device__ __forceinline__ void ldsm4(uint32_t* r, uint32_t addr) {
    asm volatile("ldmatrix.sync.aligned.m8n8.x4.shared.b16 {%0,%1,%2,%3}, [%4];"
        : "=r"(r[0]), "=r"(r[1]), "=r"(r[2]), "=r"(r[3]) : "r"(addr));
}
__device__ __forceinline__ void mma16816(float* c, const uint32_t* a, uint32_t b0, uint32_t b1) {
    asm volatile("mma.sync.aligned.m16n8k16.row.col.f32.f16.f16.f32 "
        "{%0,%1,%2,%3}, {%4,%5,%6,%7}, {%8,%9}, {%0,%1,%2,%3};"
        : "+f"(c[0]), "+f"(c[1]), "+f"(c[2]), "+f"(c[3])
        : "r"(a[0]), "r"(a[1]), "r"(a[2]), "r"(a[3]), "r"(b0), "r"(b1));
}

// E = exp(sigmoid(x)-0.5); f-values pre-halved:
//   xh = x/2; tanh(xh) = 2*sigmoid(x)-1 => E = exp2(tanh(xh)*log2(e)/2)
__device__ __forceinline__ float e_of(float a, float f12h) {
    float xh = a * f12h, t, r;
    asm("tanh.approx.f32 %0, %1;" : "=f"(t) : "f"(xh));
    float y = t * 0.72134752f;
    asm("ex2.approx.f32 %0, %1;" : "=f"(r) : "f"(y));
    return r;
}

// ---------------- kernel 1: h = node_rep @ proj_W^T + proj_b -------------------
__global__ __launch_bounds__(256) void k_proj(const float* __restrict__ node_rep,
                                              const float* __restrict__ proj_W,
                                              const float* __restrict__ proj_b) {
    __shared__ float pw[C_OUT][C_IN + 1];
    __shared__ float nr[16][C_IN];
    int tid = threadIdx.x;
    for (int k = tid; k < C_OUT * C_IN; k += 256)
        pw[k / C_IN][k % C_IN] = proj_W[k];
    int row0 = blockIdx.x * 16;
    for (int k = tid; k < 16 * C_IN; k += 256)
        nr[k / C_IN][k % C_IN] = node_rep[(row0 + k / C_IN) * C_IN + (k % C_IN)];
    __syncthreads();
    int o  = tid & 63;
    int rg = tid >> 6;
    float bias = proj_b[o];
    #pragma unroll
    for (int rr = 0; rr < 4; rr++) {
        int r = rg * 4 + rr;
        float acc = bias;
        #pragma unroll 16
        for (int c = 0; c < C_IN; c++) acc += nr[r][c] * pw[o][c];
        g_h[(row0 + r) * C_OUT + o] = acc;
    }
}

// ---------------- kernel 2: halved own-type gate scalars -----------------------
__global__ __launch_bounds__(256) void k_scores(const int*   __restrict__ node_type,
                                                const float* __restrict__ k_W,
                                                const float* __restrict__ k_b,
                                                const float* __restrict__ v_W,
                                                const float* __restrict__ v_b) {
    int warp = threadIdx.x >> 5;
    int lane = threadIdx.x & 31;
    int row  = blockIdx.x * 8 + warp;
    int t = node_type[row & (NN - 1)];
    float h0 = g_h[row * 64 + lane];
    float h1 = g_h[row * 64 + lane + 32];
    float p1 = h0 * k_W[t * 64 + lane] + h1 * k_W[t * 64 + lane + 32];
    float p2 = h0 * v_W[t * 64 + lane] + h1 * v_W[t * 64 + lane + 32];
    #pragma unroll
    for (int off = 16; off; off >>= 1) {
        p1 += __shfl_down_sync(0xffffffffu, p1, off);
        p2 += __shfl_down_sync(0xffffffffu, p2, off);
    }
    if (lane == 0) {
        g_f1[row] = 0.5f * (p1 + k_b[t]);
        g_f2[row] = 0.5f * (p2 + v_b[t]);
    }
}

// ---------------- kernel 3: partial column sums --------------------------------
__global__ __launch_bounds__(128) void k_colsum(const float* __restrict__ adj) {
    int j  = blockIdx.x * 128 + threadIdx.x;
    int rc = blockIdx.y;
    float f2v[BB], s[BB];
    #pragma unroll
    for (int b = 0; b < BB; b++) { f2v[b] = g_f2[b * NN + j]; s[b] = 0.0f; }
    int i0 = rc * 128;
    for (int ii = 0; ii < 128; ii++) {
        int i = i0 + ii;
        float a = adj[i * NN + j];
        #pragma unroll
        for (int b = 0; b < BB; b++)
            s[b] += e_of(a, g_f1[b * NN + i] + f2v[b]);
    }
    #pragma unroll
    for (int b = 0; b < BB; b++)
        g_Sp[(rc * BB + b) * NN + j] = s[b];
}

// ---------------- kernel 4: rS = 4096/S ------------------------------------------
__global__ __launch_bounds__(256) void k_reduceS() {
    int idx = blockIdx.x * 256 + threadIdx.x;
    float s = 0.0f;
    #pragma unroll
    for (int rc = 0; rc < ROWCHUNKS; rc++) s += g_Sp[rc * BB * NN + idx];
    g_rS[idx] = __fdividef(4096.0f, s);
}

// ---------------- kernel 4b: g_hT[b][o][j] = fp16(h[b][j][o] * rS[b][j]) --------
__global__ __launch_bounds__(256) void k_prep() {
    int idx = blockIdx.x * 256 + threadIdx.x;      // over BB*64*NN/2
    int jp = idx & (NN / 2 - 1);
    int bo = idx / (NN / 2);
    int o = bo & 63, b = bo >> 6;
    int j0 = jp * 2;
    float r0 = g_rS[b * NN + j0], r1 = g_rS[b * NN + j0 + 1];
    float v0 = g_h[((size_t)b * NN + j0) * 64 + o] * r0;
    float v1 = g_h[((size_t)b * NN + j0 + 1) * 64 + o] * r1;
    *(uint32_t*)&g_hT[((size_t)b * 64 + o) * NN + j0] = pack_f16(v0, v1);
}

// ---------------- kernel 5: out = E @ h2^T, pipelined HMMA ----------------------
// CTA: 64 i x 64 o, 8 warps: mw = wid&3 (16-row block), nw = wid>>2 (32-col block).
__global__ __launch_bounds__(256)
void k_main_mma(const float* __restrict__ adj, float* __restrict__ out) {
    extern __shared__ __align__(16) char dyn[];
    __shared__ float f1s[ITILE];

    int tid  = threadIdx.x;
    int wid  = tid >> 5;
    int lane = tid & 31;
    int it = blockIdx.x, b = blockIdx.y;
    int i0 = it * ITILE;

    int mw = wid & 3;
    int nw = wid >> 2;

    if (tid < ITILE) f1s[tid] = g_f1[b * NN + i0 + tid];

    const float4* adj4 = (const float4*)adj;
    const float4* f24  = (const float4*)(g_f2 + b * NN);

    uint32_t base = smem_u32(dyn);
    uint32_t eA[2] = { base,          base + BUFB };
    uint32_t hB[2] = { base + EBYTES, base + BUFB + EBYTES };
    uint16_t* Ep[2] = { (uint16_t*)dyn,            (uint16_t*)(dyn + BUFB) };
    uint16_t* Hp[2] = { (uint16_t*)(dyn + EBYTES), (uint16_t*)(dyn + BUFB + EBYTES) };

    // staging decomposition
    int si  = tid >> 4;               // E: base i-row (x4 strided by 16), 0..15
    int sjq = tid & 15;               // E: float4 column
    int ho  = tid >> 2;               // H: o row (0..63)
    int hseg = tid & 3;               // H: 16-half segment
    const uint4* hsrc = (const uint4*)&g_hT[((size_t)b * 64 + ho) * NN];

    float acc[4][4];
    #pragma unroll
    for (int nt = 0; nt < 4; nt++)
        #pragma unroll
        for (int q = 0; q < 4; q++) acc[nt][q] = 0.0f;

    float4 pa[4];
    #pragma unroll
    for (int k2 = 0; k2 < 4; k2++)
        pa[k2] = adj4[(size_t)(i0 + si + 16 * k2) * (NN / 4) + sjq];
    __syncthreads();   // f1s ready

    // ---- stage chunk 0 into buf 0 ----
    {
        float4 f2 = f24[sjq];
        #pragma unroll
        for (int k2 = 0; k2 < 4; k2++) {
            int i = si + 16 * k2;
            float4 a = pa[k2];
            float f1 = f1s[i];
            *(uint2*)&Ep[0][i * ESTR + sjq * 4] = make_uint2(
                pack_f16(e_of(a.x, f1 + f2.x), e_of(a.y, f1 + f2.y)),
                pack_f16(e_of(a.z, f1 + f2.z), e_of(a.w, f1 + f2.w)));
        }
        uint4* hdst = (uint4*)&Hp[0][ho * ESTR + hseg * 16];
        hdst[0] = hsrc[hseg * 2];
        hdst[1] = hsrc[hseg * 2 + 1];
    }
    __syncthreads();

    int rowl = lane & 15;
    int koff = 8 * (lane >> 4);

    for (int c = 0; c < 64; c++) {
        int buf = c & 1;

        // prefetch adj for chunk c+1 (covered by MMA below)
        if (c + 1 < 64) {
            #pragma unroll
            for (int k2 = 0; k2 < 4; k2++)
                pa[k2] = adj4[(size_t)(i0 + si + 16 * k2) * (NN / 4) + (c + 1) * 16 + sjq];
        }

        // ---- MMA on buf(c): per warp 16x32 out, K=64 ----
        #pragma unroll
        for (int ks = 0; ks < 4; ks++) {
            int kb = ks * 16 + koff;
            uint32_t af[4], bf[2][4];
            ldsm4(af,    eA[buf] + (uint32_t)(((mw * 16 + rowl) * ESTR + kb) * 2));
            ldsm4(bf[0], hB[buf] + (uint32_t)(((nw * 32 +  0 + rowl) * ESTR + kb) * 2));
            ldsm4(bf[1], hB[buf] + (uint32_t)(((nw * 32 + 16 + rowl) * ESTR + kb) * 2));
            mma16816(acc[0], af, bf[0][0], bf[0][2]);
            mma16816(acc[1], af, bf[0][1], bf[0][3]);
            mma16816(acc[2], af, bf[1][0], bf[1][2]);
            mma16816(acc[3], af, bf[1][1], bf[1][3]);
        }

        // ---- stage chunk c+1 into buf^1 ----
        if (c + 1 < 64) {
            int nb = buf ^ 1;
            int j0q = (c + 1) * 16;
            float4 f2 = f24[j0q + sjq];
            #pragma unroll
            for (int k2 = 0; k2 < 4; k2++) {
                int i = si + 16 * k2;
                float4 a = pa[k2];
                float f1 = f1s[i];
                *(uint2*)&Ep[nb][i * ESTR + sjq * 4] = make_uint2(
                    pack_f16(e_of(a.x, f1 + f2.x), e_of(a.y, f1 + f2.y)),
                    pack_f16(e_of(a.z, f1 + f2.z), e_of(a.w, f1 + f2.w)));
            }
            uint4* hdst = (uint4*)&Hp[nb][ho * ESTR + hseg * 16];
            hdst[0] = hsrc[(c + 1) * 8 + hseg * 2];
            hdst[1] = hsrc[(c + 1) * 8 + hseg * 2 + 1];
        }
        __syncthreads();
    }

    // ---- epilogue: undo 4096 pre-scale (exact pow2), store f32 ----
    const float sc = 1.0f / 4096.0f;
    int rr = lane >> 2;
    int cc = (lane & 3) * 2;
    #pragma unroll
    for (int nt = 0; nt < 4; nt++) {
        size_t row = (size_t)b * NN + i0 + mw * 16 + rr;
        int col = nw * 32 + nt * 8 + cc;
        *(float2*)(out + row * 64 + col) =
            make_float2(acc[nt][0] * sc, acc[nt][1] * sc);
        *(float2*)(out + (row + 8) * 64 + col) =
            make_float2(acc[nt][2] * sc, acc[nt][3] * sc);
    }
}

// ---------------- launch ---------------------------------------------------------
extern "C" void kernel_launch(void* const* d_in, const int* in_sizes, int n_in,
                              void* d_out, int out_size) {
    const float* node_rep = (const float*)d_in[0];
    const float* adj      = (const float*)d_in[1];
    const int*   node_ty  = (const int*)  d_in[2];
    const float* proj_W   = (const float*)d_in[3];
    const float* proj_b   = (const float*)d_in[4];
    const float* k_W      = (const float*)d_in[5];
    const float* k_b      = (const float*)d_in[6];
    const float* v_W      = (const float*)d_in[7];
    const float* v_b      = (const float*)d_in[8];
    float* out = (float*)d_out;

    k_proj    <<<(BB * NN) / 16, 256>>>(node_rep, proj_W, proj_b);
    k_scores  <<<(BB * NN) / 8, 256>>>(node_ty, k_W, k_b, v_W, v_b);
    k_colsum  <<<dim3(NN / 128, ROWCHUNKS), 128>>>(adj);
    k_reduceS <<<(BB * NN) / 256, 256>>>();
    k_prep    <<<(BB * 64 * NN / 2) / 256, 256>>>();
    k_main_mma<<<dim3(NN / ITILE, BB), 256, SMEM_DYN>>>(adj, out);
}

// round 9
// speedup vs baseline: 4.6481x; 1.0831x over previous
#include <cuda_runtime.h>
#include <cuda_fp16.h>
#include <cstdint>

#define NN 4096
#define BB 4
#define C_IN 128
#define C_OUT 64
#define ROWCHUNKS 32
#define ITILE 64
#define KCH 128                      // K elements per chunk
#define CHUNKS (NN / KCH)            // 32
#define ESTR2 136                    // padded half-stride: 272B rows (68 words, +4 banks/row)
#define TILEB (64 * ESTR2 * 2)       // 17408 bytes per tile
#define BUFB  (2 * TILEB)            // E + H
#define SMEM_DYN (2 * BUFB)          // 69632 (double buffered)

// ---------------- scratch -----------------------------------------------------
__device__ float    g_h  [BB * NN * C_OUT];
__device__ float    g_f1 [BB * NN];          // 0.5 * own-type k score
__device__ float    g_f2 [BB * NN];          // 0.5 * own-type v score
__device__ float    g_Sp [ROWCHUNKS * BB * NN];
__device__ float    g_rS [BB * NN];          // 4096 / S
__device__ uint16_t g_hT [BB * 64 * NN];     // fp16 (h*rS)^T, [b][o][j]
__device__ uint16_t g_E  [(size_t)BB * NN * NN];  // fp16 unnormalized E, [b][i][j]

// ---------------- helpers ------------------------------------------------------
__device__ __forceinline__ uint32_t smem_u32(const void* p) {
    uint32_t a;
    asm("{ .reg .u64 t; cvta.to.shared.u64 t, %1; cvt.u32.u64 %0, t; }" : "=r"(a) : "l"(p));
    return a;
}
__device__ __forceinline__ uint32_t pack_f16(float lo, float hi) {
    uint32_t r;
    asm("cvt.rn.f16x2.f32 %0, %1, %2;" : "=r"(r) : "f"(hi), "f"(lo));
    return r;
}
__device__ __forceinline__ void cp16(uint32_t dst, const void* src) {
    asm volatile("cp.async.cg.shared.global [%0], [%1], 16;" :: "r"(dst), "l"(src) : "memory");
}
__device__ __forceinline__ void ldsm4(uint32_t* r, uint32_t addr) {
    asm volatile("ldmatrix.sync.aligned.m8n8.x4.shared.b16 {%0,%1,%2,%3}, [%4];"
        : "=r"(r[0]), "=r"(r[1]), "=r"(r[2]), "=r"(r[3]) : "r"(addr));
}
__device__ __forceinline__ void mma16816(float* c, const uint32_t* a, uint32_t b0, uint32_t b1) {
    asm volatile("mma.sync.aligned.m16n8k16.row.col.f32.f16.f16.f32 "
        "{%0,%1,%2,%3}, {%4,%5,%6,%7}, {%8,%9}, {%0,%1,%2,%3};"
        : "+f"(c[0]), "+f"(c[1]), "+f"(c[2]), "+f"(c[3])
        : "r"(a[0]), "r"(a[1]), "r"(a[2]), "r"(a[3]), "r"(b0), "r"(b1));
}

// E = exp(sigmoid(x)-0.5); f-values pre-halved:
//   xh = x/2; tanh(xh) = 2*sigmoid(x)-1 => E = exp2(tanh(xh)*log2(e)/2)
__device__ __forceinline__ float e_of(float a, float f12h) {
    float xh = a * f12h, t, r;
    asm("tanh.approx.f32 %0, %1;" : "=f"(t) : "f"(xh));
    float y = t * 0.72134752f;
    asm("ex2.approx.f32 %0, %1;" : "=f"(r) : "f"(y));
    return r;
}

// ---------------- kernel 1: h = node_rep @ proj_W^T + proj_b -------------------
__global__ __launch_bounds__(256) void k_proj(const float* __restrict__ node_rep,
                                              const float* __restrict__ proj_W,
                                              const float* __restrict__ proj_b) {
    __shared__ float pw[C_OUT][C_IN + 1];
    __shared__ float nr[16][C_IN];
    int tid = threadIdx.x;
    for (int k = tid; k < C_OUT * C_IN; k += 256)
        pw[k / C_IN][k % C_IN] = proj_W[k];
    int row0 = blockIdx.x * 16;
    for (int k = tid; k < 16 * C_IN; k += 256)
        nr[k / C_IN][k % C_IN] = node_rep[(row0 + k / C_IN) * C_IN + (k % C_IN)];
    __syncthreads();
    int o  = tid & 63;
    int rg = tid >> 6;
    float bias = proj_b[o];
    #pragma unroll
    for (int rr = 0; rr < 4; rr++) {
        int r = rg * 4 + rr;
        float acc = bias;
        #pragma unroll 16
        for (int c = 0; c < C_IN; c++) acc += nr[r][c] * pw[o][c];
        g_h[(row0 + r) * C_OUT + o] = acc;
    }
}

// ---------------- kernel 2: halved own-type gate scalars -----------------------
__global__ __launch_bounds__(256) void k_scores(const int*   __restrict__ node_type,
                                                const float* __restrict__ k_W,
                                                const float* __restrict__ k_b,
                                                const float* __restrict__ v_W,
                                                const float* __restrict__ v_b) {
    int warp = threadIdx.x >> 5;
    int lane = threadIdx.x & 31;
    int row  = blockIdx.x * 8 + warp;
    int t = node_type[row & (NN - 1)];
    float h0 = g_h[row * 64 + lane];
    float h1 = g_h[row * 64 + lane + 32];
    float p1 = h0 * k_W[t * 64 + lane] + h1 * k_W[t * 64 + lane + 32];
    float p2 = h0 * v_W[t * 64 + lane] + h1 * v_W[t * 64 + lane + 32];
    #pragma unroll
    for (int off = 16; off; off >>= 1) {
        p1 += __shfl_down_sync(0xffffffffu, p1, off);
        p2 += __shfl_down_sync(0xffffffffu, p2, off);
    }
    if (lane == 0) {
        g_f1[row] = 0.5f * (p1 + k_b[t]);
        g_f2[row] = 0.5f * (p2 + v_b[t]);
    }
}

// ---------------- kernel 3: column sums + materialize E fp16 -------------------
// block: 128 threads, each owns a j-pair. grid: (NN/256, ROWCHUNKS).
__global__ __launch_bounds__(128) void k_colsumE(const float* __restrict__ adj) {
    __shared__ float f1s[BB][128];
    int tid = threadIdx.x;
    int j0 = blockIdx.x * 256 + tid * 2;
    int i0 = blockIdx.y * 128;

    for (int k = tid; k < BB * 128; k += 128) {
        int b = k >> 7, ii = k & 127;
        f1s[b][ii] = g_f1[b * NN + i0 + ii];
    }
    __syncthreads();

    float f2x[BB], f2y[BB], sx[BB], sy[BB];
    #pragma unroll
    for (int b = 0; b < BB; b++) {
        f2x[b] = g_f2[b * NN + j0];
        f2y[b] = g_f2[b * NN + j0 + 1];
        sx[b] = 0.0f; sy[b] = 0.0f;
    }

    for (int ii = 0; ii < 128; ii++) {
        int i = i0 + ii;
        float2 a = *(const float2*)(adj + (size_t)i * NN + j0);
        #pragma unroll
        for (int b = 0; b < BB; b++) {
            float f1 = f1s[b][ii];
            float e0 = e_of(a.x, f1 + f2x[b]);
            float e1 = e_of(a.y, f1 + f2y[b]);
            sx[b] += e0; sy[b] += e1;
            *(uint32_t*)&g_E[((size_t)b * NN + i) * NN + j0] = pack_f16(e0, e1);
        }
    }
    #pragma unroll
    for (int b = 0; b < BB; b++)
        *(float2*)&g_Sp[(size_t)(blockIdx.y * BB + b) * NN + j0] = make_float2(sx[b], sy[b]);
}

// ---------------- kernel 4: rS = 4096/S ------------------------------------------
__global__ __launch_bounds__(256) void k_reduceS() {
    int idx = blockIdx.x * 256 + threadIdx.x;
    float s = 0.0f;
    #pragma unroll
    for (int rc = 0; rc < ROWCHUNKS; rc++) s += g_Sp[rc * BB * NN + idx];
    g_rS[idx] = __fdividef(4096.0f, s);
}

// ---------------- kernel 4b: g_hT[b][o][j] = fp16(h[b][j][o] * rS[b][j]) --------
__global__ __launch_bounds__(256) void k_prep() {
    int idx = blockIdx.x * 256 + threadIdx.x;
    int jp = idx & (NN / 2 - 1);
    int bo = idx / (NN / 2);
    int o = bo & 63, b = bo >> 6;
    int j0 = jp * 2;
    float r0 = g_rS[b * NN + j0], r1 = g_rS[b * NN + j0 + 1];
    float v0 = g_h[((size_t)b * NN + j0) * 64 + o] * r0;
    float v1 = g_h[((size_t)b * NN + j0 + 1) * 64 + o] * r1;
    *(uint32_t*)&g_hT[((size_t)b * 64 + o) * NN + j0] = pack_f16(v0, v1);
}

// ---------------- kernel 5: pure fp16 GEMM, E streamed via cp.async -------------
// CTA: 64 i x 64 o, 8 warps: mw = wid&3 (16-row block), nw = wid>>2 (32-col block).
__global__ __launch_bounds__(256)
void k_main_mma(float* __restrict__ out) {
    extern __shared__ __align__(16) char dyn[];

    int tid  = threadIdx.x;
    int wid  = tid >> 5;
    int lane = tid & 31;
    int it = blockIdx.x, b = blockIdx.y;
    int i0 = it * ITILE;

    int mw = wid & 3;
    int nw = wid >> 2;

    uint32_t base = smem_u32(dyn);
    uint32_t eA[2] = { base,         base + BUFB };
    uint32_t hB[2] = { base + TILEB, base + BUFB + TILEB };

    // staging decomposition: 1024 16B segments per tile, 4 per thread
    int srow = tid >> 4;          // 0..15 (strided by 16 -> rows 0..63)
    int sseg = tid & 15;          // 16B segment within 256B row
    const uint16_t* esrc0 = &g_E[((size_t)b * NN + i0) * NN];
    const uint16_t* hsrc0 = &g_hT[(size_t)b * 64 * NN];

    float acc[4][4];
    #pragma unroll
    for (int nt = 0; nt < 4; nt++)
        #pragma unroll
        for (int q = 0; q < 4; q++) acc[nt][q] = 0.0f;

    // ---- prologue: stage chunk 0 into buf 0 ----
    #pragma unroll
    for (int k2 = 0; k2 < 4; k2++) {
        int row = srow + 16 * k2;
        cp16(eA[0] + (uint32_t)(row * (ESTR2 * 2) + sseg * 16),
             esrc0 + (size_t)row * NN + sseg * 8);
        cp16(hB[0] + (uint32_t)(row * (ESTR2 * 2) + sseg * 16),
             hsrc0 + (size_t)row * NN + sseg * 8);
    }
    asm volatile("cp.async.commit_group;" ::: "memory");

    int rowl = lane & 15;
    int koff = 8 * (lane >> 4);

    for (int c = 0; c < CHUNKS; c++) {
        int buf = c & 1;

        // stage chunk c+1 into the other buffer (its readers finished last iter)
        if (c + 1 < CHUNKS) {
            int nb = buf ^ 1;
            #pragma unroll
            for (int k2 = 0; k2 < 4; k2++) {
                int row = srow + 16 * k2;
                cp16(eA[nb] + (uint32_t)(row * (ESTR2 * 2) + sseg * 16),
                     esrc0 + (size_t)row * NN + (c + 1) * KCH + sseg * 8);
                cp16(hB[nb] + (uint32_t)(row * (ESTR2 * 2) + sseg * 16),
                     hsrc0 + (size_t)row * NN + (c + 1) * KCH + sseg * 8);
            }
        }
        asm volatile("cp.async.commit_group;" ::: "memory");
        asm volatile("cp.async.wait_group 1;" ::: "memory");
        __syncthreads();   // chunk c resident for all warps

        // ---- MMA on buf(c): per warp 16x32 out, K=128 ----
        #pragma unroll
        for (int ks = 0; ks < 8; ks++) {
            int kb = ks * 16 + koff;
            uint32_t af[4], bf0[4], bf1[4];
            ldsm4(af,  eA[buf] + (uint32_t)(((mw * 16 + rowl) * ESTR2 + kb) * 2));
            ldsm4(bf0, hB[buf] + (uint32_t)(((nw * 32 +  0 + rowl) * ESTR2 + kb) * 2));
            ldsm4(bf1, hB[buf] + (uint32_t)(((nw * 32 + 16 + rowl) * ESTR2 + kb) * 2));
            mma16816(acc[0], af, bf0[0], bf0[2]);
            mma16816(acc[1], af, bf0[1], bf0[3]);
            mma16816(acc[2], af, bf1[0], bf1[2]);
            mma16816(acc[3], af, bf1[1], bf1[3]);
        }
        __syncthreads();   // all warps done reading buf before it is overwritten
    }

    // ---- epilogue: undo 4096 pre-scale (exact pow2), store f32 ----
    const float sc = 1.0f / 4096.0f;
    int rr = lane >> 2;
    int cc = (lane & 3) * 2;
    #pragma unroll
    for (int nt = 0; nt < 4; nt++) {
        size_t row = (size_t)b * NN + i0 + mw * 16 + rr;
        int col = nw * 32 + nt * 8 + cc;
        *(float2*)(out + row * 64 + col) =
            make_float2(acc[nt][0] * sc, acc[nt][1] * sc);
        *(float2*)(out + (row + 8) * 64 + col) =
            make_float2(acc[nt][2] * sc, acc[nt][3] * sc);
    }
}

// ---------------- launch ---------------------------------------------------------
extern "C" void kernel_launch(void* const* d_in, const int* in_sizes, int n_in,
                              void* d_out, int out_size) {
    const float* node_rep = (const float*)d_in[0];
    const float* adj      = (const float*)d_in[1];
    const int*   node_ty  = (const int*)  d_in[2];
    const float* proj_W   = (const float*)d_in[3];
    const float* proj_b   = (const float*)d_in[4];
    const float* k_W      = (const float*)d_in[5];
    const float* k_b      = (const float*)d_in[6];
    const float* v_W      = (const float*)d_in[7];
    const float* v_b      = (const float*)d_in[8];
    float* out = (float*)d_out;

    static bool attr_done = false;
    if (!attr_done) {
        cudaFuncSetAttribute(k_main_mma, cudaFuncAttributeMaxDynamicSharedMemorySize, SMEM_DYN);
        attr_done = true;
    }

    k_proj    <<<(BB * NN) / 16, 256>>>(node_rep, proj_W, proj_b);
    k_scores  <<<(BB * NN) / 8, 256>>>(node_ty, k_W, k_b, v_W, v_b);
    k_colsumE <<<dim3(NN / 256, ROWCHUNKS), 128>>>(adj);
    k_reduceS <<<(BB * NN) / 256, 256>>>();
    k_prep    <<<(BB * 64 * NN / 2) / 256, 256>>>();
    k_main_mma<<<dim3(NN / ITILE, BB), 256, SMEM_DYN>>>(out);
}

// round 10
// speedup vs baseline: 4.6905x; 1.0091x over previous
#include <cuda_runtime.h>
#include <cuda_fp16.h>
#include <cstdint>

#define NN 4096
#define BB 4
#define C_IN 128
#define C_OUT 64
#define ROWCHUNKS 32
#define ITILE 64
#define KCH 128                      // K elements per chunk
#define CHUNKS (NN / KCH)            // 32
#define ESTR2 136                    // padded half-stride: 272B rows
#define TILEB (64 * ESTR2 * 2)       // 17408 bytes per tile
#define BUFB  (2 * TILEB)            // E + H
#define SMEM_DYN (2 * BUFB)          // 69632 (double buffered)

// ---------------- scratch -----------------------------------------------------
__device__ float    g_h  [BB * NN * C_OUT];
__device__ float    g_f1 [BB * NN];          // 0.5 * own-type k score
__device__ float    g_f2 [BB * NN];          // 0.5 * own-type v score
__device__ float    g_Sp [ROWCHUNKS * BB * NN];
__device__ float    g_rS [BB * NN];          // 4096 / S
__device__ uint16_t g_hT [BB * 64 * NN];     // fp16 (h*rS)^T, [b][o][j]
__device__ uint16_t g_E  [(size_t)BB * NN * NN];  // fp16 unnormalized E, [b][i][j]

// ---------------- helpers ------------------------------------------------------
__device__ __forceinline__ uint32_t smem_u32(const void* p) {
    uint32_t a;
    asm("{ .reg .u64 t; cvta.to.shared.u64 t, %1; cvt.u32.u64 %0, t; }" : "=r"(a) : "l"(p));
    return a;
}
__device__ __forceinline__ uint32_t pack_f16(float lo, float hi) {
    uint32_t r;
    asm("cvt.rn.f16x2.f32 %0, %1, %2;" : "=r"(r) : "f"(hi), "f"(lo));
    return r;
}
__device__ __forceinline__ void cp16(uint32_t dst, const void* src) {
    asm volatile("cp.async.cg.shared.global [%0], [%1], 16;" :: "r"(dst), "l"(src) : "memory");
}
__device__ __forceinline__ void ldsm4(uint32_t* r, uint32_t addr) {
    asm volatile("ldmatrix.sync.aligned.m8n8.x4.shared.b16 {%0,%1,%2,%3}, [%4];"
        : "=r"(r[0]), "=r"(r[1]), "=r"(r[2]), "=r"(r[3]) : "r"(addr));
}
__device__ __forceinline__ void mma16816(float* c, const uint32_t* a, uint32_t b0, uint32_t b1) {
    asm volatile("mma.sync.aligned.m16n8k16.row.col.f32.f16.f16.f32 "
        "{%0,%1,%2,%3}, {%4,%5,%6,%7}, {%8,%9}, {%0,%1,%2,%3};"
        : "+f"(c[0]), "+f"(c[1]), "+f"(c[2]), "+f"(c[3])
        : "r"(a[0]), "r"(a[1]), "r"(a[2]), "r"(a[3]), "r"(b0), "r"(b1));
}

// E = exp(sigmoid(x)-0.5); f-values pre-halved: t = tanh(x/2) = 2*sigmoid(x)-1,
// E = exp(t/2) via deg-5 Horner (R3-validated, |err| < 3e-5). 1 MUFU + 6 FMA.
__device__ __forceinline__ float e_of(float a, float f12h) {
    float xh = a * f12h, t;
    asm("tanh.approx.f32 %0, %1;" : "=f"(t) : "f"(xh));
    float p = fmaf(t, 2.604166667e-4f, 2.604166667e-3f);
    p = fmaf(p, t, 2.083333333e-2f);
    p = fmaf(p, t, 0.125f);
    p = fmaf(p, t, 0.5f);
    p = fmaf(p, t, 1.0f);
    return p;
}

// ---------------- kernel 1: proj + fused gate scalars ---------------------------
__global__ __launch_bounds__(256) void k_proj(const float* __restrict__ node_rep,
                                              const float* __restrict__ proj_W,
                                              const float* __restrict__ proj_b,
                                              const int*   __restrict__ node_type,
                                              const float* __restrict__ k_W,
                                              const float* __restrict__ k_b,
                                              const float* __restrict__ v_W,
                                              const float* __restrict__ v_b) {
    __shared__ float pw[C_OUT][C_IN + 1];
    __shared__ float nr[16][C_IN];
    __shared__ float hs[16][C_OUT + 1];
    int tid = threadIdx.x;
    for (int k = tid; k < C_OUT * C_IN; k += 256)
        pw[k / C_IN][k % C_IN] = proj_W[k];
    int row0 = blockIdx.x * 16;
    for (int k = tid; k < 16 * C_IN; k += 256)
        nr[k / C_IN][k % C_IN] = node_rep[(row0 + k / C_IN) * C_IN + (k % C_IN)];
    __syncthreads();
    int o  = tid & 63;
    int rg = tid >> 6;
    float bias = proj_b[o];
    #pragma unroll
    for (int rr = 0; rr < 4; rr++) {
        int r = rg * 4 + rr;
        float acc = bias;
        #pragma unroll 16
        for (int c = 0; c < C_IN; c++) acc += nr[r][c] * pw[o][c];
        g_h[(row0 + r) * C_OUT + o] = acc;
        hs[r][o] = acc;
    }
    __syncthreads();

    // fused k_scores: each warp reduces 2 rows
    int warp = tid >> 5, lane = tid & 31;
    #pragma unroll
    for (int rr = 0; rr < 2; rr++) {
        int r = warp * 2 + rr;
        int grow = row0 + r;                 // flattened b*N + n
        int t = node_type[grow & (NN - 1)];
        float h0 = hs[r][lane], h1 = hs[r][lane + 32];
        float p1 = h0 * k_W[t * 64 + lane] + h1 * k_W[t * 64 + lane + 32];
        float p2 = h0 * v_W[t * 64 + lane] + h1 * v_W[t * 64 + lane + 32];
        #pragma unroll
        for (int off = 16; off; off >>= 1) {
            p1 += __shfl_down_sync(0xffffffffu, p1, off);
            p2 += __shfl_down_sync(0xffffffffu, p2, off);
        }
        if (lane == 0) {
            g_f1[grow] = 0.5f * (p1 + k_b[t]);
            g_f2[grow] = 0.5f * (p2 + v_b[t]);
        }
    }
}

// ---------------- kernel 2: column sums + materialize E fp16 -------------------
__global__ __launch_bounds__(128) void k_colsumE(const float* __restrict__ adj) {
    __shared__ float f1s[BB][128];
    int tid = threadIdx.x;
    int j0 = blockIdx.x * 256 + tid * 2;
    int i0 = blockIdx.y * 128;

    for (int k = tid; k < BB * 128; k += 128) {
        int b = k >> 7, ii = k & 127;
        f1s[b][ii] = g_f1[b * NN + i0 + ii];
    }
    __syncthreads();

    float f2x[BB], f2y[BB], sx[BB], sy[BB];
    #pragma unroll
    for (int b = 0; b < BB; b++) {
        f2x[b] = g_f2[b * NN + j0];
        f2y[b] = g_f2[b * NN + j0 + 1];
        sx[b] = 0.0f; sy[b] = 0.0f;
    }

    for (int ii = 0; ii < 128; ii++) {
        int i = i0 + ii;
        float2 a = *(const float2*)(adj + (size_t)i * NN + j0);
        #pragma unroll
        for (int b = 0; b < BB; b++) {
            float f1 = f1s[b][ii];
            float e0 = e_of(a.x, f1 + f2x[b]);
            float e1 = e_of(a.y, f1 + f2y[b]);
            sx[b] += e0; sy[b] += e1;
            *(uint32_t*)&g_E[((size_t)b * NN + i) * NN + j0] = pack_f16(e0, e1);
        }
    }
    #pragma unroll
    for (int b = 0; b < BB; b++)
        *(float2*)&g_Sp[(size_t)(blockIdx.y * BB + b) * NN + j0] = make_float2(sx[b], sy[b]);
}

// ---------------- kernel 3: rS = 4096/S ------------------------------------------
__global__ __launch_bounds__(256) void k_reduceS() {
    int idx = blockIdx.x * 256 + threadIdx.x;
    float s = 0.0f;
    #pragma unroll
    for (int rc = 0; rc < ROWCHUNKS; rc++) s += g_Sp[rc * BB * NN + idx];
    g_rS[idx] = __fdividef(4096.0f, s);
}

// ---------------- kernel 3b: g_hT[b][o][j] = fp16(h[b][j][o] * rS[b][j]) --------
__global__ __launch_bounds__(256) void k_prep() {
    int idx = blockIdx.x * 256 + threadIdx.x;
    int jp = idx & (NN / 2 - 1);
    int bo = idx / (NN / 2);
    int o = bo & 63, b = bo >> 6;
    int j0 = jp * 2;
    float r0 = g_rS[b * NN + j0], r1 = g_rS[b * NN + j0 + 1];
    float v0 = g_h[((size_t)b * NN + j0) * 64 + o] * r0;
    float v1 = g_h[((size_t)b * NN + j0 + 1) * 64 + o] * r1;
    *(uint32_t*)&g_hT[((size_t)b * 64 + o) * NN + j0] = pack_f16(v0, v1);
}

// ---------------- kernel 4: pure fp16 GEMM, E streamed via cp.async -------------
__global__ __launch_bounds__(256)
void k_main_mma(float* __restrict__ out) {
    extern __shared__ __align__(16) char dyn[];

    int tid  = threadIdx.x;
    int wid  = tid >> 5;
    int lane = tid & 31;
    int it = blockIdx.x, b = blockIdx.y;
    int i0 = it * ITILE;

    int mw = wid & 3;
    int nw = wid >> 2;

    uint32_t base = smem_u32(dyn);
    uint32_t eA[2] = { base,         base + BUFB };
    uint32_t hB[2] = { base + TILEB, base + BUFB + TILEB };

    int srow = tid >> 4;
    int sseg = tid & 15;
    const uint16_t* esrc0 = &g_E[((size_t)b * NN + i0) * NN];
    const uint16_t* hsrc0 = &g_hT[(size_t)b * 64 * NN];

    float acc[4][4];
    #pragma unroll
    for (int nt = 0; nt < 4; nt++)
        #pragma unroll
        for (int q = 0; q < 4; q++) acc[nt][q] = 0.0f;

    #pragma unroll
    for (int k2 = 0; k2 < 4; k2++) {
        int row = srow + 16 * k2;
        cp16(eA[0] + (uint32_t)(row * (ESTR2 * 2) + sseg * 16),
             esrc0 + (size_t)row * NN + sseg * 8);
        cp16(hB[0] + (uint32_t)(row * (ESTR2 * 2) + sseg * 16),
             hsrc0 + (size_t)row * NN + sseg * 8);
    }
    asm volatile("cp.async.commit_group;" ::: "memory");

    int rowl = lane & 15;
    int koff = 8 * (lane >> 4);

    for (int c = 0; c < CHUNKS; c++) {
        int buf = c & 1;

        if (c + 1 < CHUNKS) {
            int nb = buf ^ 1;
            #pragma unroll
            for (int k2 = 0; k2 < 4; k2++) {
                int row = srow + 16 * k2;
                cp16(eA[nb] + (uint32_t)(row * (ESTR2 * 2) + sseg * 16),
                     esrc0 + (size_t)row * NN + (c + 1) * KCH + sseg * 8);
                cp16(hB[nb] + (uint32_t)(row * (ESTR2 * 2) + sseg * 16),
                     hsrc0 + (size_t)row * NN + (c + 1) * KCH + sseg * 8);
            }
        }
        asm volatile("cp.async.commit_group;" ::: "memory");
        asm volatile("cp.async.wait_group 1;" ::: "memory");
        __syncthreads();

        #pragma unroll
        for (int ks = 0; ks < 8; ks++) {
            int kb = ks * 16 + koff;
            uint32_t af[4], bf0[4], bf1[4];
            ldsm4(af,  eA[buf] + (uint32_t)(((mw * 16 + rowl) * ESTR2 + kb) * 2));
            ldsm4(bf0, hB[buf] + (uint32_t)(((nw * 32 +  0 + rowl) * ESTR2 + kb) * 2));
            ldsm4(bf1, hB[buf] + (uint32_t)(((nw * 32 + 16 + rowl) * ESTR2 + kb) * 2));
            mma16816(acc[0], af, bf0[0], bf0[2]);
            mma16816(acc[1], af, bf0[1], bf0[3]);
            mma16816(acc[2], af, bf1[0], bf1[2]);
            mma16816(acc[3], af, bf1[1], bf1[3]);
        }
        __syncthreads();
    }

    const float sc = 1.0f / 4096.0f;
    int rr = lane >> 2;
    int cc = (lane & 3) * 2;
    #pragma unroll
    for (int nt = 0; nt < 4; nt++) {
        size_t row = (size_t)b * NN + i0 + mw * 16 + rr;
        int col = nw * 32 + nt * 8 + cc;
        *(float2*)(out + row * 64 + col) =
            make_float2(acc[nt][0] * sc, acc[nt][1] * sc);
        *(float2*)(out + (row + 8) * 64 + col) =
            make_float2(acc[nt][2] * sc, acc[nt][3] * sc);
    }
}

// ---------------- launch ---------------------------------------------------------
extern "C" void kernel_launch(void* const* d_in, const int* in_sizes, int n_in,
                              void* d_out, int out_size) {
    const float* node_rep = (const float*)d_in[0];
    const float* adj      = (const float*)d_in[1];
    const int*   node_ty  = (const int*)  d_in[2];
    const float* proj_W   = (const float*)d_in[3];
    const float* proj_b   = (const float*)d_in[4];
    const float* k_W      = (const float*)d_in[5];
    const float* k_b      = (const float*)d_in[6];
    const float* v_W      = (const float*)d_in[7];
    const float* v_b      = (const float*)d_in[8];
    float* out = (float*)d_out;

    static bool attr_done = false;
    if (!attr_done) {
        cudaFuncSetAttribute(k_main_mma, cudaFuncAttributeMaxDynamicSharedMemorySize, SMEM_DYN);
        attr_done = true;
    }

    k_proj    <<<(BB * NN) / 16, 256>>>(node_rep, proj_W, proj_b,
                                        node_ty, k_W, k_b, v_W, v_b);
    k_colsumE <<<dim3(NN / 256, ROWCHUNKS), 128>>>(adj);
    k_reduceS <<<(BB * NN) / 256, 256>>>();
    k_prep    <<<(BB * 64 * NN / 2) / 256, 256>>>();
    k_main_mma<<<dim3(NN / ITILE, BB), 256, SMEM_DYN>>>(out);
}

// round 11
// speedup vs baseline: 5.5751x; 1.1886x over previous
#include <cuda_runtime.h>
#include <cuda_fp16.h>
#include <cstdint>

#define NN 4096
#define BB 4
#define C_IN 128
#define C_OUT 64
#define ICH 64                        // i-rows per colsumE block
#define RCHUNK (NN / ICH)             // 64 partial-sum chunks
#define ITILE 64
#define KCH 128                       // K elements per chunk
#define CHUNKS (NN / KCH)             // 32
#define ESTR2 136                     // padded half-stride: 272B rows
#define TILEB (64 * ESTR2 * 2)        // 17408 bytes per tile
#define BUFB  (2 * TILEB)             // E + H
#define SMEM_DYN (2 * BUFB)           // 69632 (double buffered)

// ---------------- scratch -----------------------------------------------------
__device__ float    g_h  [BB * NN * C_OUT];
__device__ float    g_f1 [BB * NN];          // 0.5 * own-type k score
__device__ float    g_f2 [BB * NN];          // 0.5 * own-type v score
__device__ float    g_Sp [RCHUNK * BB * NN];
__device__ float    g_rS [BB * NN];          // 4096 / S
__device__ uint16_t g_hT [BB * 64 * NN];     // fp16 (h*rS)^T, [b][o][j]
__device__ uint16_t g_E  [(size_t)BB * NN * NN];  // fp16 unnormalized E, [b][i][j]

// ---------------- helpers ------------------------------------------------------
__device__ __forceinline__ uint32_t smem_u32(const void* p) {
    uint32_t a;
    asm("{ .reg .u64 t; cvta.to.shared.u64 t, %1; cvt.u32.u64 %0, t; }" : "=r"(a) : "l"(p));
    return a;
}
__device__ __forceinline__ uint32_t pack_f16(float lo, float hi) {
    uint32_t r;
    asm("cvt.rn.f16x2.f32 %0, %1, %2;" : "=r"(r) : "f"(hi), "f"(lo));
    return r;
}
__device__ __forceinline__ void cp16(uint32_t dst, const void* src) {
    asm volatile("cp.async.cg.shared.global [%0], [%1], 16;" :: "r"(dst), "l"(src) : "memory");
}
__device__ __forceinline__ void ldsm4(uint32_t* r, uint32_t addr) {
    asm volatile("ldmatrix.sync.aligned.m8n8.x4.shared.b16 {%0,%1,%2,%3}, [%4];"
        : "=r"(r[0]), "=r"(r[1]), "=r"(r[2]), "=r"(r[3]) : "r"(addr));
}
__device__ __forceinline__ void mma16816(float* c, const uint32_t* a, uint32_t b0, uint32_t b1) {
    asm volatile("mma.sync.aligned.m16n8k16.row.col.f32.f16.f16.f32 "
        "{%0,%1,%2,%3}, {%4,%5,%6,%7}, {%8,%9}, {%0,%1,%2,%3};"
        : "+f"(c[0]), "+f"(c[1]), "+f"(c[2]), "+f"(c[3])
        : "r"(a[0]), "r"(a[1]), "r"(a[2]), "r"(a[3]), "r"(b0), "r"(b1));
}

// E = exp(sigmoid(x)-0.5); f-values pre-halved: t = tanh(x/2) = 2*sigmoid(x)-1,
// E = exp(t/2) via deg-5 Horner (|err| < 3e-5). 1 MUFU + 6 FMA.
__device__ __forceinline__ float e_of(float a, float f12h) {
    float xh = a * f12h, t;
    asm("tanh.approx.f32 %0, %1;" : "=f"(t) : "f"(xh));
    float p = fmaf(t, 2.604166667e-4f, 2.604166667e-3f);
    p = fmaf(p, t, 2.083333333e-2f);
    p = fmaf(p, t, 0.125f);
    p = fmaf(p, t, 0.5f);
    p = fmaf(p, t, 1.0f);
    return p;
}

// ---------------- kernel 1: proj + fused gate scalars ---------------------------
__global__ __launch_bounds__(256) void k_proj(const float* __restrict__ node_rep,
                                              const float* __restrict__ proj_W,
                                              const float* __restrict__ proj_b,
                                              const int*   __restrict__ node_type,
                                              const float* __restrict__ k_W,
                                              const float* __restrict__ k_b,
                                              const float* __restrict__ v_W,
                                              const float* __restrict__ v_b) {
    __shared__ float pw[C_OUT][C_IN + 1];
    __shared__ float nr[16][C_IN];
    __shared__ float hs[16][C_OUT + 1];
    int tid = threadIdx.x;
    for (int k = tid; k < C_OUT * C_IN; k += 256)
        pw[k / C_IN][k % C_IN] = proj_W[k];
    int row0 = blockIdx.x * 16;
    for (int k = tid; k < 16 * C_IN; k += 256)
        nr[k / C_IN][k % C_IN] = node_rep[(row0 + k / C_IN) * C_IN + (k % C_IN)];
    __syncthreads();
    int o  = tid & 63;
    int rg = tid >> 6;
    float bias = proj_b[o];
    #pragma unroll
    for (int rr = 0; rr < 4; rr++) {
        int r = rg * 4 + rr;
        float acc = bias;
        #pragma unroll 16
        for (int c = 0; c < C_IN; c++) acc += nr[r][c] * pw[o][c];
        g_h[(row0 + r) * C_OUT + o] = acc;
        hs[r][o] = acc;
    }
    __syncthreads();

    int warp = tid >> 5, lane = tid & 31;
    #pragma unroll
    for (int rr = 0; rr < 2; rr++) {
        int r = warp * 2 + rr;
        int grow = row0 + r;
        int t = node_type[grow & (NN - 1)];
        float h0 = hs[r][lane], h1 = hs[r][lane + 32];
        float p1 = h0 * k_W[t * 64 + lane] + h1 * k_W[t * 64 + lane + 32];
        float p2 = h0 * v_W[t * 64 + lane] + h1 * v_W[t * 64 + lane + 32];
        #pragma unroll
        for (int off = 16; off; off >>= 1) {
            p1 += __shfl_down_sync(0xffffffffu, p1, off);
            p2 += __shfl_down_sync(0xffffffffu, p2, off);
        }
        if (lane == 0) {
            g_f1[grow] = 0.5f * (p1 + k_b[t]);
            g_f2[grow] = 0.5f * (p2 + v_b[t]);
        }
    }
}

// ---------------- kernel 2: column sums + materialize E fp16 -------------------
// grid (NN/256, NN/ICH); 128 threads; each thread 2 j x 4 b over ICH i-rows.
__global__ __launch_bounds__(128) void k_colsumE(const float* __restrict__ adj) {
    __shared__ float f1s[BB][ICH];
    int tid = threadIdx.x;
    int j0 = blockIdx.x * 256 + tid * 2;
    int i0 = blockIdx.y * ICH;

    for (int k = tid; k < BB * ICH; k += 128) {
        int b = k / ICH, ii = k % ICH;
        f1s[b][ii] = g_f1[b * NN + i0 + ii];
    }
    __syncthreads();

    float f2x[BB], f2y[BB], sx[BB], sy[BB];
    #pragma unroll
    for (int b = 0; b < BB; b++) {
        f2x[b] = g_f2[b * NN + j0];
        f2y[b] = g_f2[b * NN + j0 + 1];
        sx[b] = 0.0f; sy[b] = 0.0f;
    }

    for (int ii = 0; ii < ICH; ii++) {
        int i = i0 + ii;
        float2 a = *(const float2*)(adj + (size_t)i * NN + j0);
        #pragma unroll
        for (int b = 0; b < BB; b++) {
            float f1 = f1s[b][ii];
            float e0 = e_of(a.x, f1 + f2x[b]);
            float e1 = e_of(a.y, f1 + f2y[b]);
            sx[b] += e0; sy[b] += e1;
            *(uint32_t*)&g_E[((size_t)b * NN + i) * NN + j0] = pack_f16(e0, e1);
        }
    }
    #pragma unroll
    for (int b = 0; b < BB; b++)
        *(float2*)&g_Sp[(size_t)(blockIdx.y * BB + b) * NN + j0] = make_float2(sx[b], sy[b]);
}

// ---------------- kernel 3: rS = 4096/S ------------------------------------------
__global__ __launch_bounds__(256) void k_reduceS() {
    int idx = blockIdx.x * 256 + threadIdx.x;
    float s = 0.0f;
    #pragma unroll
    for (int rc = 0; rc < RCHUNK; rc++) s += g_Sp[rc * BB * NN + idx];
    g_rS[idx] = __fdividef(4096.0f, s);
}

// ---------------- kernel 3b: coalesced transpose h*rS -> fp16 hT ----------------
// grid (NN/64, BB), 256 threads; 64 j x 64 o tile via smem.
__global__ __launch_bounds__(256) void k_prep() {
    __shared__ float ts[64][65];
    int b = blockIdx.y, j0 = blockIdx.x * 64;
    int tid = threadIdx.x;
    #pragma unroll
    for (int k = tid; k < 64 * 64; k += 256) {
        int jj = k >> 6, o = k & 63;
        ts[jj][o] = g_h[((size_t)(b * NN + j0 + jj)) * 64 + o] * g_rS[b * NN + j0 + jj];
    }
    __syncthreads();
    int o = tid >> 2, seg = tid & 3;
    uint32_t* dst = (uint32_t*)&g_hT[((size_t)b * 64 + o) * NN + j0 + seg * 16];
    #pragma unroll
    for (int q = 0; q < 8; q++) {
        int j = seg * 16 + q * 2;
        dst[q] = pack_f16(ts[j][o], ts[j + 1][o]);
    }
}

// ---------------- kernel 4: pure fp16 GEMM, E streamed via cp.async -------------
// One __syncthreads per chunk; LDSM fragments double-buffered inside MMA phase.
__global__ __launch_bounds__(256)
void k_main_mma(float* __restrict__ out) {
    extern __shared__ __align__(16) char dyn[];

    int tid  = threadIdx.x;
    int wid  = tid >> 5;
    int lane = tid & 31;
    int it = blockIdx.x, b = blockIdx.y;
    int i0 = it * ITILE;

    int mw = wid & 3;
    int nw = wid >> 2;

    uint32_t base = smem_u32(dyn);
    uint32_t eA[2] = { base,         base + BUFB };
    uint32_t hB[2] = { base + TILEB, base + BUFB + TILEB };

    int srow = tid >> 4;
    int sseg = tid & 15;
    const uint16_t* esrc0 = &g_E[((size_t)b * NN + i0) * NN];
    const uint16_t* hsrc0 = &g_hT[(size_t)b * 64 * NN];

    float acc[4][4];
    #pragma unroll
    for (int nt = 0; nt < 4; nt++)
        #pragma unroll
        for (int q = 0; q < 4; q++) acc[nt][q] = 0.0f;

    // prologue: stage chunk 0 into buf 0
    #pragma unroll
    for (int k2 = 0; k2 < 4; k2++) {
        int row = srow + 16 * k2;
        cp16(eA[0] + (uint32_t)(row * (ESTR2 * 2) + sseg * 16),
             esrc0 + (size_t)row * NN + sseg * 8);
        cp16(hB[0] + (uint32_t)(row * (ESTR2 * 2) + sseg * 16),
             hsrc0 + (size_t)row * NN + sseg * 8);
    }
    asm volatile("cp.async.commit_group;" ::: "memory");

    int rowl = lane & 15;
    int koff = 8 * (lane >> 4);
    uint32_t aBase = (uint32_t)(((mw * 16 + rowl) * ESTR2 + koff) * 2);
    uint32_t bBase0 = (uint32_t)(((nw * 32 + rowl) * ESTR2 + koff) * 2);
    uint32_t bBase1 = (uint32_t)(((nw * 32 + 16 + rowl) * ESTR2 + koff) * 2);

    for (int c = 0; c < CHUNKS; c++) {
        int buf = c & 1;

        asm volatile("cp.async.wait_group 0;" ::: "memory");
        __syncthreads();   // buf c ready AND all warps finished MMA(c-1)

        // stage chunk c+1 (async; overlaps MMA below)
        if (c + 1 < CHUNKS) {
            int nb = buf ^ 1;
            #pragma unroll
            for (int k2 = 0; k2 < 4; k2++) {
                int row = srow + 16 * k2;
                cp16(eA[nb] + (uint32_t)(row * (ESTR2 * 2) + sseg * 16),
                     esrc0 + (size_t)row * NN + (c + 1) * KCH + sseg * 8);
                cp16(hB[nb] + (uint32_t)(row * (ESTR2 * 2) + sseg * 16),
                     hsrc0 + (size_t)row * NN + (c + 1) * KCH + sseg * 8);
            }
            asm volatile("cp.async.commit_group;" ::: "memory");
        }

        // MMA phase with fragment double-buffering
        uint32_t af[2][4], bf0[2][4], bf1[2][4];
        ldsm4(af[0],  eA[buf] + aBase);
        ldsm4(bf0[0], hB[buf] + bBase0);
        ldsm4(bf1[0], hB[buf] + bBase1);
        #pragma unroll
        for (int ks = 0; ks < 8; ks++) {
            int cur = ks & 1, nxt = cur ^ 1;
            if (ks < 7) {
                uint32_t kadd = (uint32_t)((ks + 1) * 16 * 2);
                ldsm4(af[nxt],  eA[buf] + aBase  + kadd);
                ldsm4(bf0[nxt], hB[buf] + bBase0 + kadd);
                ldsm4(bf1[nxt], hB[buf] + bBase1 + kadd);
            }
            mma16816(acc[0], af[cur], bf0[cur][0], bf0[cur][2]);
            mma16816(acc[1], af[cur], bf0[cur][1], bf0[cur][3]);
            mma16816(acc[2], af[cur], bf1[cur][0], bf1[cur][2]);
            mma16816(acc[3], af[cur], bf1[cur][1], bf1[cur][3]);
        }
    }

    const float sc = 1.0f / 4096.0f;
    int rr = lane >> 2;
    int cc = (lane & 3) * 2;
    #pragma unroll
    for (int nt = 0; nt < 4; nt++) {
        size_t row = (size_t)b * NN + i0 + mw * 16 + rr;
        int col = nw * 32 + nt * 8 + cc;
        *(float2*)(out + row * 64 + col) =
            make_float2(acc[nt][0] * sc, acc[nt][1] * sc);
        *(float2*)(out + (row + 8) * 64 + col) =
            make_float2(acc[nt][2] * sc, acc[nt][3] * sc);
    }
}

// ---------------- launch ---------------------------------------------------------
extern "C" void kernel_launch(void* const* d_in, const int* in_sizes, int n_in,
                              void* d_out, int out_size) {
    const float* node_rep = (const float*)d_in[0];
    const float* adj      = (const float*)d_in[1];
    const int*   node_ty  = (const int*)  d_in[2];
    const float* proj_W   = (const float*)d_in[3];
    const float* proj_b   = (const float*)d_in[4];
    const float* k_W      = (const float*)d_in[5];
    const float* k_b      = (const float*)d_in[6];
    const float* v_W      = (const float*)d_in[7];
    const float* v_b      = (const float*)d_in[8];
    float* out = (float*)d_out;

    static bool attr_done = false;
    if (!attr_done) {
        cudaFuncSetAttribute(k_main_mma, cudaFuncAttributeMaxDynamicSharedMemorySize, SMEM_DYN);
        attr_done = true;
    }

    k_proj    <<<(BB * NN) / 16, 256>>>(node_rep, proj_W, proj_b,
                                        node_ty, k_W, k_b, v_W, v_b);
    k_colsumE <<<dim3(NN / 256, NN / ICH), 128>>>(adj);
    k_reduceS <<<(BB * NN) / 256, 256>>>();
    k_prep    <<<dim3(NN / 64, BB), 256>>>();
    k_main_mma<<<dim3(NN / ITILE, BB), 256, SMEM_DYN>>>(out);
}

// round 12
// speedup vs baseline: 5.7439x; 1.0303x over previous
#include <cuda_runtime.h>
#include <cuda_fp16.h>
#include <cstdint>

#define NN 4096
#define BB 4
#define C_IN 128
#define C_OUT 64
#define ICH 32                        // i-rows per colsumE block
#define RCHUNK (NN / ICH)             // 128 partial-sum chunks
#define ITILE 64
#define KCH 128                       // K elements per chunk
#define CHUNKS (NN / KCH)             // 32
#define ESTR2 136                     // padded half-stride: 272B rows
#define TILEB (64 * ESTR2 * 2)        // 17408 bytes per tile
#define BUFB  (2 * TILEB)             // E + H
#define SMEM_DYN (2 * BUFB)           // 69632 (double buffered)

// ---------------- scratch -----------------------------------------------------
__device__ float    g_h  [BB * NN * C_OUT];
__device__ float    g_f1 [BB * NN];          // 0.5 * own-type k score
__device__ float    g_f2 [BB * NN];          // 0.5 * own-type v score
__device__ float    g_Sp [RCHUNK * BB * NN];
__device__ uint16_t g_hT [BB * 64 * NN];     // fp16 (h*rS)^T, [b][o][j]
__device__ uint16_t g_E  [(size_t)BB * NN * NN];  // fp16 unnormalized E, [b][i][j]

// ---------------- helpers ------------------------------------------------------
__device__ __forceinline__ uint32_t smem_u32(const void* p) {
    uint32_t a;
    asm("{ .reg .u64 t; cvta.to.shared.u64 t, %1; cvt.u32.u64 %0, t; }" : "=r"(a) : "l"(p));
    return a;
}
__device__ __forceinline__ uint32_t pack_f16(float lo, float hi) {
    uint32_t r;
    asm("cvt.rn.f16x2.f32 %0, %1, %2;" : "=r"(r) : "f"(hi), "f"(lo));
    return r;
}
__device__ __forceinline__ void cp16(uint32_t dst, const void* src) {
    asm volatile("cp.async.cg.shared.global [%0], [%1], 16;" :: "r"(dst), "l"(src) : "memory");
}
__device__ __forceinline__ void ldsm4(uint32_t* r, uint32_t addr) {
    asm volatile("ldmatrix.sync.aligned.m8n8.x4.shared.b16 {%0,%1,%2,%3}, [%4];"
        : "=r"(r[0]), "=r"(r[1]), "=r"(r[2]), "=r"(r[3]) : "r"(addr));
}
__device__ __forceinline__ void mma16816(float* c, const uint32_t* a, uint32_t b0, uint32_t b1) {
    asm volatile("mma.sync.aligned.m16n8k16.row.col.f32.f16.f16.f32 "
        "{%0,%1,%2,%3}, {%4,%5,%6,%7}, {%8,%9}, {%0,%1,%2,%3};"
        : "+f"(c[0]), "+f"(c[1]), "+f"(c[2]), "+f"(c[3])
        : "r"(a[0]), "r"(a[1]), "r"(a[2]), "r"(a[3]), "r"(b0), "r"(b1));
}

// E = exp(sigmoid(x)-0.5); f-values pre-halved: t = tanh(x/2) = 2*sigmoid(x)-1,
// E = exp(t/2) via deg-5 Horner (|err| < 3e-5). 1 MUFU + 6 FMA.
__device__ __forceinline__ float e_of(float a, float f12h) {
    float xh = a * f12h, t;
    asm("tanh.approx.f32 %0, %1;" : "=f"(t) : "f"(xh));
    float p = fmaf(t, 2.604166667e-4f, 2.604166667e-3f);
    p = fmaf(p, t, 2.083333333e-2f);
    p = fmaf(p, t, 0.125f);
    p = fmaf(p, t, 0.5f);
    p = fmaf(p, t, 1.0f);
    return p;
}

// ---------------- kernel 1: proj (float4 LDS) + fused gate scalars --------------
__global__ __launch_bounds__(256) void k_proj(const float* __restrict__ node_rep,
                                              const float* __restrict__ proj_W,
                                              const float* __restrict__ proj_b,
                                              const int*   __restrict__ node_type,
                                              const float* __restrict__ k_W,
                                              const float* __restrict__ k_b,
                                              const float* __restrict__ v_W,
                                              const float* __restrict__ v_b) {
    __shared__ __align__(16) float pw[C_OUT][C_IN + 4];  // 132-float rows: 16B-aligned
    __shared__ __align__(16) float nr[16][C_IN];
    __shared__ float hs[16][C_OUT + 1];
    int tid = threadIdx.x;
    for (int k = tid; k < C_OUT * C_IN; k += 256)
        pw[k / C_IN][k % C_IN] = proj_W[k];
    int row0 = blockIdx.x * 16;
    for (int k = tid; k < 16 * C_IN; k += 256)
        nr[k / C_IN][k % C_IN] = node_rep[(row0 + k / C_IN) * C_IN + (k % C_IN)];
    __syncthreads();
    int o  = tid & 63;
    int rg = tid >> 6;
    float bias = proj_b[o];
    const float4* pw4 = (const float4*)&pw[o][0];
    #pragma unroll
    for (int rr = 0; rr < 4; rr++) {
        int r = rg * 4 + rr;
        const float4* nr4 = (const float4*)&nr[r][0];
        float acc = 0.0f;
        #pragma unroll 8
        for (int c4 = 0; c4 < C_IN / 4; c4++) {
            float4 a = nr4[c4], w = pw4[c4];
            acc += a.x * w.x + a.y * w.y + a.z * w.z + a.w * w.w;
        }
        acc += bias;
        g_h[(row0 + r) * C_OUT + o] = acc;
        hs[r][o] = acc;
    }
    __syncthreads();

    int warp = tid >> 5, lane = tid & 31;
    #pragma unroll
    for (int rr = 0; rr < 2; rr++) {
        int r = warp * 2 + rr;
        int grow = row0 + r;
        int t = node_type[grow & (NN - 1)];
        float h0 = hs[r][lane], h1 = hs[r][lane + 32];
        float p1 = h0 * k_W[t * 64 + lane] + h1 * k_W[t * 64 + lane + 32];
        float p2 = h0 * v_W[t * 64 + lane] + h1 * v_W[t * 64 + lane + 32];
        #pragma unroll
        for (int off = 16; off; off >>= 1) {
            p1 += __shfl_down_sync(0xffffffffu, p1, off);
            p2 += __shfl_down_sync(0xffffffffu, p2, off);
        }
        if (lane == 0) {
            g_f1[grow] = 0.5f * (p1 + k_b[t]);
            g_f2[grow] = 0.5f * (p2 + v_b[t]);
        }
    }
}

// ---------------- kernel 2: column sums + materialize E fp16 -------------------
// grid (NN/256, NN/ICH); 128 threads; each thread 2 j x 4 b over ICH i-rows.
__global__ __launch_bounds__(128) void k_colsumE(const float* __restrict__ adj) {
    __shared__ float f1s[BB][ICH];
    int tid = threadIdx.x;
    int j0 = blockIdx.x * 256 + tid * 2;
    int i0 = blockIdx.y * ICH;

    if (tid < BB * ICH) {
        int b = tid / ICH, ii = tid % ICH;
        f1s[b][ii] = g_f1[b * NN + i0 + ii];
    }
    __syncthreads();

    float f2x[BB], f2y[BB], sx[BB], sy[BB];
    #pragma unroll
    for (int b = 0; b < BB; b++) {
        f2x[b] = g_f2[b * NN + j0];
        f2y[b] = g_f2[b * NN + j0 + 1];
        sx[b] = 0.0f; sy[b] = 0.0f;
    }

    for (int ii = 0; ii < ICH; ii++) {
        int i = i0 + ii;
        float2 a = *(const float2*)(adj + (size_t)i * NN + j0);
        #pragma unroll
        for (int b = 0; b < BB; b++) {
            float f1 = f1s[b][ii];
            float e0 = e_of(a.x, f1 + f2x[b]);
            float e1 = e_of(a.y, f1 + f2y[b]);
            sx[b] += e0; sy[b] += e1;
            *(uint32_t*)&g_E[((size_t)b * NN + i) * NN + j0] = pack_f16(e0, e1);
        }
    }
    #pragma unroll
    for (int b = 0; b < BB; b++)
        *(float2*)&g_Sp[(size_t)(blockIdx.y * BB + b) * NN + j0] = make_float2(sx[b], sy[b]);
}

// ---------------- kernel 3: fused rS + transpose -> fp16 hT ---------------------
// grid (NN/64, BB), 256 threads. Phase 1: reduce Sp -> rS (smem). Phase 2: hT.
__global__ __launch_bounds__(256) void k_finalize() {
    __shared__ float red[4][64];
    __shared__ float rSs[64];
    __shared__ float ts[64][65];
    int b = blockIdx.y, j0 = blockIdx.x * 64;
    int tid = threadIdx.x;

    // phase 1: 4 threads per j, each sums 32 of the 128 partials (coalesced over j)
    {
        int j = tid & 63, seg = tid >> 6;
        float s = 0.0f;
        #pragma unroll 8
        for (int k = 0; k < RCHUNK / 4; k++) {
            int rc = seg * (RCHUNK / 4) + k;
            s += g_Sp[(size_t)(rc * BB + b) * NN + j0 + j];
        }
        red[seg][j] = s;
    }
    __syncthreads();
    if (tid < 64)
        rSs[tid] = __fdividef(4096.0f, red[0][tid] + red[1][tid] + red[2][tid] + red[3][tid]);
    __syncthreads();

    // phase 2: coalesced transpose h*rS -> hT
    #pragma unroll
    for (int k = tid; k < 64 * 64; k += 256) {
        int jj = k >> 6, o = k & 63;
        ts[jj][o] = g_h[((size_t)(b * NN + j0 + jj)) * 64 + o] * rSs[jj];
    }
    __syncthreads();
    int o = tid >> 2, seg = tid & 3;
    uint32_t* dst = (uint32_t*)&g_hT[((size_t)b * 64 + o) * NN + j0 + seg * 16];
    #pragma unroll
    for (int q = 0; q < 8; q++) {
        int j = seg * 16 + q * 2;
        dst[q] = pack_f16(ts[j][o], ts[j + 1][o]);
    }
}

// ---------------- kernel 4: pure fp16 GEMM, E streamed via cp.async -------------
__global__ __launch_bounds__(256)
void k_main_mma(float* __restrict__ out) {
    extern __shared__ __align__(16) char dyn[];

    int tid  = threadIdx.x;
    int wid  = tid >> 5;
    int lane = tid & 31;
    int it = blockIdx.x, b = blockIdx.y;
    int i0 = it * ITILE;

    int mw = wid & 3;
    int nw = wid >> 2;

    uint32_t base = smem_u32(dyn);
    uint32_t eA[2] = { base,         base + BUFB };
    uint32_t hB[2] = { base + TILEB, base + BUFB + TILEB };

    int srow = tid >> 4;
    int sseg = tid & 15;
    const uint16_t* esrc0 = &g_E[((size_t)b * NN + i0) * NN];
    const uint16_t* hsrc0 = &g_hT[(size_t)b * 64 * NN];

    float acc[4][4];
    #pragma unroll
    for (int nt = 0; nt < 4; nt++)
        #pragma unroll
        for (int q = 0; q < 4; q++) acc[nt][q] = 0.0f;

    #pragma unroll
    for (int k2 = 0; k2 < 4; k2++) {
        int row = srow + 16 * k2;
        cp16(eA[0] + (uint32_t)(row * (ESTR2 * 2) + sseg * 16),
             esrc0 + (size_t)row * NN + sseg * 8);
        cp16(hB[0] + (uint32_t)(row * (ESTR2 * 2) + sseg * 16),
             hsrc0 + (size_t)row * NN + sseg * 8);
    }
    asm volatile("cp.async.commit_group;" ::: "memory");

    int rowl = lane & 15;
    int koff = 8 * (lane >> 4);
    uint32_t aBase = (uint32_t)(((mw * 16 + rowl) * ESTR2 + koff) * 2);
    uint32_t bBase0 = (uint32_t)(((nw * 32 + rowl) * ESTR2 + koff) * 2);
    uint32_t bBase1 = (uint32_t)(((nw * 32 + 16 + rowl) * ESTR2 + koff) * 2);

    for (int c = 0; c < CHUNKS; c++) {
        int buf = c & 1;

        asm volatile("cp.async.wait_group 0;" ::: "memory");
        __syncthreads();   // buf c ready AND all warps finished MMA(c-1)

        if (c + 1 < CHUNKS) {
            int nb = buf ^ 1;
            #pragma unroll
            for (int k2 = 0; k2 < 4; k2++) {
                int row = srow + 16 * k2;
                cp16(eA[nb] + (uint32_t)(row * (ESTR2 * 2) + sseg * 16),
                     esrc0 + (size_t)row * NN + (c + 1) * KCH + sseg * 8);
                cp16(hB[nb] + (uint32_t)(row * (ESTR2 * 2) + sseg * 16),
                     hsrc0 + (size_t)row * NN + (c + 1) * KCH + sseg * 8);
            }
            asm volatile("cp.async.commit_group;" ::: "memory");
        }

        uint32_t af[2][4], bf0[2][4], bf1[2][4];
        ldsm4(af[0],  eA[buf] + aBase);
        ldsm4(bf0[0], hB[buf] + bBase0);
        ldsm4(bf1[0], hB[buf] + bBase1);
        #pragma unroll
        for (int ks = 0; ks < 8; ks++) {
            int cur = ks & 1, nxt = cur ^ 1;
            if (ks < 7) {
                uint32_t kadd = (uint32_t)((ks + 1) * 16 * 2);
                ldsm4(af[nxt],  eA[buf] + aBase  + kadd);
                ldsm4(bf0[nxt], hB[buf] + bBase0 + kadd);
                ldsm4(bf1[nxt], hB[buf] + bBase1 + kadd);
            }
            mma16816(acc[0], af[cur], bf0[cur][0], bf0[cur][2]);
            mma16816(acc[1], af[cur], bf0[cur][1], bf0[cur][3]);
            mma16816(acc[2], af[cur], bf1[cur][0], bf1[cur][2]);
            mma16816(acc[3], af[cur], bf1[cur][1], bf1[cur][3]);
        }
    }

    const float sc = 1.0f / 4096.0f;
    int rr = lane >> 2;
    int cc = (lane & 3) * 2;
    #pragma unroll
    for (int nt = 0; nt < 4; nt++) {
        size_t row = (size_t)b * NN + i0 + mw * 16 + rr;
        int col = nw * 32 + nt * 8 + cc;
        *(float2*)(out + row * 64 + col) =
            make_float2(acc[nt][0] * sc, acc[nt][1] * sc);
        *(float2*)(out + (row + 8) * 64 + col) =
            make_float2(acc[nt][2] * sc, acc[nt][3] * sc);
    }
}

// ---------------- launch ---------------------------------------------------------
extern "C" void kernel_launch(void* const* d_in, const int* in_sizes, int n_in,
                              void* d_out, int out_size) {
    const float* node_rep = (const float*)d_in[0];
    const float* adj      = (const float*)d_in[1];
    const int*   node_ty  = (const int*)  d_in[2];
    const float* proj_W   = (const float*)d_in[3];
    const float* proj_b   = (const float*)d_in[4];
    const float* k_W      = (const float*)d_in[5];
    const float* k_b      = (const float*)d_in[6];
    const float* v_W      = (const float*)d_in[7];
    const float* v_b      = (const float*)d_in[8];
    float* out = (float*)d_out;

    static bool attr_done = false;
    if (!attr_done) {
        cudaFuncSetAttribute(k_main_mma, cudaFuncAttributeMaxDynamicSharedMemorySize, SMEM_DYN);
        attr_done = true;
    }

    k_proj    <<<(BB * NN) / 16, 256>>>(node_rep, proj_W, proj_b,
                                        node_ty, k_W, k_b, v_W, v_b);
    k_colsumE <<<dim3(NN / 256, NN / ICH), 128>>>(adj);
    k_finalize<<<dim3(NN / 64, BB), 256>>>();
    k_main_mma<<<dim3(NN / ITILE, BB), 256, SMEM_DYN>>>(out);
}

// round 13
// speedup vs baseline: 6.1759x; 1.0752x over previous
#include <cuda_runtime.h>
#include <cuda_fp16.h>
#include <cstdint>

#define NN 4096
#define BB 4
#define C_IN 128
#define C_OUT 64
#define ICH 32                        // i-rows per colsumE block
#define RCHUNK (NN / ICH)             // 128 partial-sum chunks
#define ITILE 64
#define KCH 128                       // K elements per chunk
#define CHUNKS (NN / KCH)             // 32
#define ESTR2 136                     // padded half-stride: 272B rows
#define TILEB (64 * ESTR2 * 2)        // 17408 bytes per tile
#define BUFB  (2 * TILEB)             // E + H = 34816
#define NSTAGE 3
#define SMEM_DYN (NSTAGE * BUFB)      // 104448 (3-stage ring)

// ---------------- scratch -----------------------------------------------------
__device__ float    g_h  [BB * NN * C_OUT];
__device__ float    g_f1 [BB * NN];          // 0.5 * own-type k score
__device__ float    g_f2 [BB * NN];          // 0.5 * own-type v score
__device__ float    g_Sp [RCHUNK * BB * NN];
__device__ uint16_t g_hT [BB * 64 * NN];     // fp16 (h*rS)^T, [b][o][j]
__device__ uint16_t g_E  [(size_t)BB * NN * NN];  // fp16 unnormalized E, [b][i][j]

// ---------------- helpers ------------------------------------------------------
__device__ __forceinline__ uint32_t smem_u32(const void* p) {
    uint32_t a;
    asm("{ .reg .u64 t; cvta.to.shared.u64 t, %1; cvt.u32.u64 %0, t; }" : "=r"(a) : "l"(p));
    return a;
}
__device__ __forceinline__ uint32_t pack_f16(float lo, float hi) {
    uint32_t r;
    asm("cvt.rn.f16x2.f32 %0, %1, %2;" : "=r"(r) : "f"(hi), "f"(lo));
    return r;
}
__device__ __forceinline__ void cp16(uint32_t dst, const void* src) {
    asm volatile("cp.async.cg.shared.global [%0], [%1], 16;" :: "r"(dst), "l"(src) : "memory");
}
__device__ __forceinline__ void ldsm4(uint32_t* r, uint32_t addr) {
    asm volatile("ldmatrix.sync.aligned.m8n8.x4.shared.b16 {%0,%1,%2,%3}, [%4];"
        : "=r"(r[0]), "=r"(r[1]), "=r"(r[2]), "=r"(r[3]) : "r"(addr));
}
__device__ __forceinline__ void mma16816(float* c, const uint32_t* a, uint32_t b0, uint32_t b1) {
    asm volatile("mma.sync.aligned.m16n8k16.row.col.f32.f16.f16.f32 "
        "{%0,%1,%2,%3}, {%4,%5,%6,%7}, {%8,%9}, {%0,%1,%2,%3};"
        : "+f"(c[0]), "+f"(c[1]), "+f"(c[2]), "+f"(c[3])
        : "r"(a[0]), "r"(a[1]), "r"(a[2]), "r"(a[3]), "r"(b0), "r"(b1));
}

// E = exp(sigmoid(x)-0.5); f-values pre-halved: t = tanh(x/2) = 2*sigmoid(x)-1,
// E = exp(t/2) via deg-5 Horner (|err| < 3e-5). 1 MUFU + 6 FMA.
__device__ __forceinline__ float e_of(float a, float f12h) {
    float xh = a * f12h, t;
    asm("tanh.approx.f32 %0, %1;" : "=f"(t) : "f"(xh));
    float p = fmaf(t, 2.604166667e-4f, 2.604166667e-3f);
    p = fmaf(p, t, 2.083333333e-2f);
    p = fmaf(p, t, 0.125f);
    p = fmaf(p, t, 0.5f);
    p = fmaf(p, t, 1.0f);
    return p;
}

// ---------------- kernel 1: proj (float4 LDS) + fused gate scalars --------------
__global__ __launch_bounds__(256) void k_proj(const float* __restrict__ node_rep,
                                              const float* __restrict__ proj_W,
                                              const float* __restrict__ proj_b,
                                              const int*   __restrict__ node_type,
                                              const float* __restrict__ k_W,
                                              const float* __restrict__ k_b,
                                              const float* __restrict__ v_W,
                                              const float* __restrict__ v_b) {
    __shared__ __align__(16) float pw[C_OUT][C_IN + 4];
    __shared__ __align__(16) float nr[16][C_IN];
    __shared__ float hs[16][C_OUT + 1];
    int tid = threadIdx.x;
    for (int k = tid; k < C_OUT * C_IN; k += 256)
        pw[k / C_IN][k % C_IN] = proj_W[k];
    int row0 = blockIdx.x * 16;
    for (int k = tid; k < 16 * C_IN; k += 256)
        nr[k / C_IN][k % C_IN] = node_rep[(row0 + k / C_IN) * C_IN + (k % C_IN)];
    __syncthreads();
    int o  = tid & 63;
    int rg = tid >> 6;
    float bias = proj_b[o];
    const float4* pw4 = (const float4*)&pw[o][0];
    #pragma unroll
    for (int rr = 0; rr < 4; rr++) {
        int r = rg * 4 + rr;
        const float4* nr4 = (const float4*)&nr[r][0];
        float acc = 0.0f;
        #pragma unroll 8
        for (int c4 = 0; c4 < C_IN / 4; c4++) {
            float4 a = nr4[c4], w = pw4[c4];
            acc += a.x * w.x + a.y * w.y + a.z * w.z + a.w * w.w;
        }
        acc += bias;
        g_h[(row0 + r) * C_OUT + o] = acc;
        hs[r][o] = acc;
    }
    __syncthreads();

    int warp = tid >> 5, lane = tid & 31;
    #pragma unroll
    for (int rr = 0; rr < 2; rr++) {
        int r = warp * 2 + rr;
        int grow = row0 + r;
        int t = node_type[grow & (NN - 1)];
        float h0 = hs[r][lane], h1 = hs[r][lane + 32];
        float p1 = h0 * k_W[t * 64 + lane] + h1 * k_W[t * 64 + lane + 32];
        float p2 = h0 * v_W[t * 64 + lane] + h1 * v_W[t * 64 + lane + 32];
        #pragma unroll
        for (int off = 16; off; off >>= 1) {
            p1 += __shfl_down_sync(0xffffffffu, p1, off);
            p2 += __shfl_down_sync(0xffffffffu, p2, off);
        }
        if (lane == 0) {
            g_f1[grow] = 0.5f * (p1 + k_b[t]);
            g_f2[grow] = 0.5f * (p2 + v_b[t]);
        }
    }
}

// ---------------- kernel 2: column sums + materialize E fp16 -------------------
// grid (NN/512, NN/ICH); 128 threads; each thread 4 j (float4) x 4 b over ICH rows.
__global__ __launch_bounds__(128) void k_colsumE(const float* __restrict__ adj) {
    __shared__ float f1s[BB][ICH];
    int tid = threadIdx.x;
    int j0 = blockIdx.x * 512 + tid * 4;
    int i0 = blockIdx.y * ICH;

    if (tid < BB * ICH) {
        int b = tid / ICH, ii = tid % ICH;
        f1s[b][ii] = g_f1[b * NN + i0 + ii];
    }
    __syncthreads();

    float4 f2v[BB], s[BB];
    #pragma unroll
    for (int b = 0; b < BB; b++) {
        f2v[b] = *(const float4*)(g_f2 + b * NN + j0);
        s[b] = make_float4(0.f, 0.f, 0.f, 0.f);
    }

    for (int ii = 0; ii < ICH; ii++) {
        int i = i0 + ii;
        float4 a = *(const float4*)(adj + (size_t)i * NN + j0);
        #pragma unroll
        for (int b = 0; b < BB; b++) {
            float f1 = f1s[b][ii];
            float e0 = e_of(a.x, f1 + f2v[b].x);
            float e1 = e_of(a.y, f1 + f2v[b].y);
            float e2 = e_of(a.z, f1 + f2v[b].z);
            float e3 = e_of(a.w, f1 + f2v[b].w);
            s[b].x += e0; s[b].y += e1; s[b].z += e2; s[b].w += e3;
            *(uint2*)&g_E[((size_t)b * NN + i) * NN + j0] =
                make_uint2(pack_f16(e0, e1), pack_f16(e2, e3));
        }
    }
    #pragma unroll
    for (int b = 0; b < BB; b++)
        *(float4*)&g_Sp[(size_t)(blockIdx.y * BB + b) * NN + j0] = s[b];
}

// ---------------- kernel 3: fused rS + transpose -> fp16 hT ---------------------
__global__ __launch_bounds__(256) void k_finalize() {
    __shared__ float red[4][64];
    __shared__ float rSs[64];
    __shared__ float ts[64][65];
    int b = blockIdx.y, j0 = blockIdx.x * 64;
    int tid = threadIdx.x;

    {
        int j = tid & 63, seg = tid >> 6;
        float s = 0.0f;
        #pragma unroll 8
        for (int k = 0; k < RCHUNK / 4; k++) {
            int rc = seg * (RCHUNK / 4) + k;
            s += g_Sp[(size_t)(rc * BB + b) * NN + j0 + j];
        }
        red[seg][j] = s;
    }
    __syncthreads();
    if (tid < 64)
        rSs[tid] = __fdividef(4096.0f, red[0][tid] + red[1][tid] + red[2][tid] + red[3][tid]);
    __syncthreads();

    #pragma unroll
    for (int k = tid; k < 64 * 64; k += 256) {
        int jj = k >> 6, o = k & 63;
        ts[jj][o] = g_h[((size_t)(b * NN + j0 + jj)) * 64 + o] * rSs[jj];
    }
    __syncthreads();
    int o = tid >> 2, seg = tid & 3;
    uint32_t* dst = (uint32_t*)&g_hT[((size_t)b * 64 + o) * NN + j0 + seg * 16];
    #pragma unroll
    for (int q = 0; q < 8; q++) {
        int j = seg * 16 + q * 2;
        dst[q] = pack_f16(ts[j][o], ts[j + 1][o]);
    }
}

// ---------------- kernel 4: fp16 GEMM, 3-stage cp.async ring --------------------
__global__ __launch_bounds__(256)
void k_main_mma(float* __restrict__ out) {
    extern __shared__ __align__(16) char dyn[];

    int tid  = threadIdx.x;
    int wid  = tid >> 5;
    int lane = tid & 31;
    int it = blockIdx.x, b = blockIdx.y;
    int i0 = it * ITILE;

    int mw = wid & 3;
    int nw = wid >> 2;

    uint32_t base = smem_u32(dyn);
    uint32_t eA[NSTAGE], hB[NSTAGE];
    #pragma unroll
    for (int s = 0; s < NSTAGE; s++) {
        eA[s] = base + s * BUFB;
        hB[s] = base + s * BUFB + TILEB;
    }

    int srow = tid >> 4;
    int sseg = tid & 15;
    const uint16_t* esrc0 = &g_E[((size_t)b * NN + i0) * NN];
    const uint16_t* hsrc0 = &g_hT[(size_t)b * 64 * NN];

    float acc[4][4];
    #pragma unroll
    for (int nt = 0; nt < 4; nt++)
        #pragma unroll
        for (int q = 0; q < 4; q++) acc[nt][q] = 0.0f;

    // prologue: stage chunks 0 and 1 (one commit group each)
    #pragma unroll
    for (int pc = 0; pc < 2; pc++) {
        #pragma unroll
        for (int k2 = 0; k2 < 4; k2++) {
            int row = srow + 16 * k2;
            cp16(eA[pc] + (uint32_t)(row * (ESTR2 * 2) + sseg * 16),
                 esrc0 + (size_t)row * NN + pc * KCH + sseg * 8);
            cp16(hB[pc] + (uint32_t)(row * (ESTR2 * 2) + sseg * 16),
                 hsrc0 + (size_t)row * NN + pc * KCH + sseg * 8);
        }
        asm volatile("cp.async.commit_group;" ::: "memory");
    }

    int rowl = lane & 15;
    int koff = 8 * (lane >> 4);
    uint32_t aBase = (uint32_t)(((mw * 16 + rowl) * ESTR2 + koff) * 2);
    uint32_t bBase0 = (uint32_t)(((nw * 32 + rowl) * ESTR2 + koff) * 2);
    uint32_t bBase1 = (uint32_t)(((nw * 32 + 16 + rowl) * ESTR2 + koff) * 2);

    int buf = 0;
    for (int c = 0; c < CHUNKS; c++) {
        // chunk c resident (one group may stay in flight)
        asm volatile("cp.async.wait_group 1;" ::: "memory");
        __syncthreads();   // all warps past MMA(c-1); buf[(c+2)%3] reusable

        // stage chunk c+2 (or commit empty group to keep the count discipline)
        if (c + 2 < CHUNKS) {
            int nb = buf + 2 >= NSTAGE ? buf + 2 - NSTAGE : buf + 2;
            #pragma unroll
            for (int k2 = 0; k2 < 4; k2++) {
                int row = srow + 16 * k2;
                cp16(eA[nb] + (uint32_t)(row * (ESTR2 * 2) + sseg * 16),
                     esrc0 + (size_t)row * NN + (c + 2) * KCH + sseg * 8);
                cp16(hB[nb] + (uint32_t)(row * (ESTR2 * 2) + sseg * 16),
                     hsrc0 + (size_t)row * NN + (c + 2) * KCH + sseg * 8);
            }
        }
        asm volatile("cp.async.commit_group;" ::: "memory");

        // MMA phase with fragment double-buffering
        uint32_t af[2][4], bf0[2][4], bf1[2][4];
        ldsm4(af[0],  eA[buf] + aBase);
        ldsm4(bf0[0], hB[buf] + bBase0);
        ldsm4(bf1[0], hB[buf] + bBase1);
        #pragma unroll
        for (int ks = 0; ks < 8; ks++) {
            int cur = ks & 1, nxt = cur ^ 1;
            if (ks < 7) {
                uint32_t kadd = (uint32_t)((ks + 1) * 16 * 2);
                ldsm4(af[nxt],  eA[buf] + aBase  + kadd);
                ldsm4(bf0[nxt], hB[buf] + bBase0 + kadd);
                ldsm4(bf1[nxt], hB[buf] + bBase1 + kadd);
            }
            mma16816(acc[0], af[cur], bf0[cur][0], bf0[cur][2]);
            mma16816(acc[1], af[cur], bf0[cur][1], bf0[cur][3]);
            mma16816(acc[2], af[cur], bf1[cur][0], bf1[cur][2]);
            mma16816(acc[3], af[cur], bf1[cur][1], bf1[cur][3]);
        }
        buf = buf + 1 >= NSTAGE ? 0 : buf + 1;
    }

    const float sc = 1.0f / 4096.0f;
    int rr = lane >> 2;
    int cc = (lane & 3) * 2;
    #pragma unroll
    for (int nt = 0; nt < 4; nt++) {
        size_t row = (size_t)b * NN + i0 + mw * 16 + rr;
        int col = nw * 32 + nt * 8 + cc;
        *(float2*)(out + row * 64 + col) =
            make_float2(acc[nt][0] * sc, acc[nt][1] * sc);
        *(float2*)(out + (row + 8) * 64 + col) =
            make_float2(acc[nt][2] * sc, acc[nt][3] * sc);
    }
}

// ---------------- launch ---------------------------------------------------------
extern "C" void kernel_launch(void* const* d_in, const int* in_sizes, int n_in,
                              void* d_out, int out_size) {
    const float* node_rep = (const float*)d_in[0];
    const float* adj      = (const float*)d_in[1];
    const int*   node_ty  = (const int*)  d_in[2];
    const float* proj_W   = (const float*)d_in[3];
    const float* proj_b   = (const float*)d_in[4];
    const float* k_W      = (const float*)d_in[5];
    const float* k_b      = (const float*)d_in[6];
    const float* v_W      = (const float*)d_in[7];
    const float* v_b      = (const float*)d_in[8];
    float* out = (float*)d_out;

    static bool attr_done = false;
    if (!attr_done) {
        cudaFuncSetAttribute(k_main_mma, cudaFuncAttributeMaxDynamicSharedMemorySize, SMEM_DYN);
        attr_done = true;
    }

    k_proj    <<<(BB * NN) / 16, 256>>>(node_rep, proj_W, proj_b,
                                        node_ty, k_W, k_b, v_W, v_b);
    k_colsumE <<<dim3(NN / 512, NN / ICH), 128>>>(adj);
    k_finalize<<<dim3(NN / 64, BB), 256>>>();
    k_main_mma<<<dim3(NN / ITILE, BB), 256, SMEM_DYN>>>(out);
}